// round 14
// baseline (speedup 1.0000x reference)
#include <cuda_runtime.h>
#include <cuda_bf16.h>
#include <cstdint>

#define Nn   200
#define NP   256
#define Bx   8
#define NCH  6400
#define GW   192

typedef __nv_bfloat16 bf16;
typedef __nv_bfloat162 bf162;

// ---------------- static scratch ----------------
__device__ float g_d0[NP];
__device__ float g_d1[NP];
__device__ float g_Afp[NP*NP];
__device__ float g_Rtf[NP*NP];
__device__ float g_R2f[NP*NP];
__device__ bf16  gA_h[NP*NP],  gA_l[NP*NP];
__device__ bf16  gRt_h[NP*NP], gRt_l[NP*NP];
__device__ bf16  gR2_h[NP*NP], gR2_l[NP*NP];
__device__ bf16  gX_h[(size_t)Bx*NP*NCH],  gX_l[(size_t)Bx*NP*NCH];
__device__ bf16  gY1_h[(size_t)Bx*NP*NCH], gY1_l[(size_t)Bx*NP*NCH];
__device__ bf16  gY2_h[(size_t)Bx*NP*NCH], gY2_l[(size_t)Bx*NP*NCH];
__device__ bf16  gW_h[128*GW], gW_l[128*GW];            // [k=128][n=192]

// ---------------- prep kernels ----------------
__global__ void k_deg(const float* __restrict__ adj) {
    int i = threadIdx.x;
    if (i < Nn) {
        float cs = 0.f, rs = 0.f;
        for (int b = 0; b < Nn; b++) if (b != i) cs += adj[b*Nn + i];
        for (int e = 0; e < Nn; e++) if (e != i) rs += adj[i*Nn + e];
        g_d0[i] = (cs > 0.f) ? rsqrtf(cs) : 0.f;
        g_d1[i] = (rs > 0.f) ? rsqrtf(rs) : 0.f;
    }
}
__global__ void k_buildA(const float* __restrict__ adj) {
    int idx = blockIdx.x * blockDim.x + threadIdx.x;
    if (idx < NP*NP) {
        int e = idx / NP, b = idx % NP;
        float v = 0.f;
        if (e < Nn && b < Nn && e != b) v = g_d0[b] * adj[b*Nn + e] * g_d1[e];
        g_Afp[e*NP + b] = v;
        g_Rtf[b*NP + e] = v;
    }
}
__global__ void k_R2() {
    __shared__ float a[16][17], b[16][17];
    int tx = threadIdx.x, ty = threadIdx.y;
    int j = blockIdx.y*16 + ty, q = blockIdx.x*16 + tx;
    float s = 0.f;
    for (int p0 = 0; p0 < NP; p0 += 16) {
        a[ty][tx] = g_Rtf[j*NP + p0 + tx];
        b[ty][tx] = g_Rtf[(p0+ty)*NP + q];
        __syncthreads();
        #pragma unroll
        for (int p = 0; p < 16; p++) s += a[ty][p]*b[p][tx];
        __syncthreads();
    }
    g_R2f[j*NP + q] = 2.f*s;
}
static __device__ __forceinline__ unsigned pack2(float a, float b) {
    bf162 t; t.x = __float2bfloat16(a); t.y = __float2bfloat16(b);
    return *reinterpret_cast<unsigned*>(&t);
}
__global__ void k_prepsplit(const float* __restrict__ x, const float* __restrict__ w) {
    int b = blockIdx.x;
    int tid = threadIdx.x;
    if (b < 768) {
        int which = b / 256;
        const float* s; bf16 *h, *l;
        if (which == 0)      { s = g_Afp; h = gA_h;  l = gA_l;  }
        else if (which == 1) { s = g_Rtf; h = gRt_h; l = gRt_l; }
        else                 { s = g_R2f; h = gR2_h; l = gR2_l; }
        int i = (b % 256)*256 + tid;
        float v = s[i];
        bf16 hh = __float2bfloat16(v);
        h[i] = hh;
        l[i] = __float2bfloat16(v - __bfloat162float(hh));
    } else if (b < 768 + 12800) {
        size_t i4 = ((size_t)(b - 768)*256 + tid) * 4;
        int col = (int)(i4 % NCH);
        int r   = (int)((i4 / NCH) % NP);
        int bb  = (int)(i4 / ((size_t)NP*NCH));
        float v0 = 0.f, v1 = 0.f, v2 = 0.f, v3 = 0.f;
        if (r < Nn) {
            const float4 xv = *reinterpret_cast<const float4*>(x + ((size_t)bb*Nn + r)*NCH + col);
            v0 = xv.x; v1 = xv.y; v2 = xv.z; v3 = xv.w;
        }
        bf16 h0 = __float2bfloat16(v0), h1 = __float2bfloat16(v1);
        bf16 h2 = __float2bfloat16(v2), h3 = __float2bfloat16(v3);
        float l0 = v0 - __bfloat162float(h0), l1 = v1 - __bfloat162float(h1);
        float l2 = v2 - __bfloat162float(h2), l3 = v3 - __bfloat162float(h3);
        bf162 ph0; ph0.x = h0; ph0.y = h1;
        bf162 ph1; ph1.x = h2; ph1.y = h3;
        uint2 hv = make_uint2(*reinterpret_cast<unsigned*>(&ph0), *reinterpret_cast<unsigned*>(&ph1));
        uint2 lv = make_uint2(pack2(l0, l1), pack2(l2, l3));
        *reinterpret_cast<uint2*>(gX_h + i4) = hv;
        *reinterpret_cast<uint2*>(gX_l + i4) = lv;
    } else {
        int i = (b - 768 - 12800)*256 + tid;
        int k = i / GW, n = i % GW;
        float v = 0.f;
        if (k < 96) {
            int k1 = k / 32, c = k & 31;
            int k2 = n / 64, o = n & 63;
            v = w[o*288 + (k1*3 + k2)*32 + c];
        }
        bf16 hh = __float2bfloat16(v);
        gW_h[i] = hh;
        gW_l[i] = __float2bfloat16(v - __bfloat162float(hh));
    }
}

// ---------------- mma/async helpers ----------------
static __device__ __forceinline__ unsigned sptr(const void* p) {
    return (unsigned)__cvta_generic_to_shared(p);
}
static __device__ __forceinline__ void mma_bf16(float* c, const unsigned* a, const unsigned* b) {
    asm volatile("mma.sync.aligned.m16n8k16.row.col.f32.bf16.bf16.f32 "
        "{%0,%1,%2,%3},{%4,%5,%6,%7},{%8,%9},{%0,%1,%2,%3};\n"
        : "+f"(c[0]), "+f"(c[1]), "+f"(c[2]), "+f"(c[3])
        : "r"(a[0]), "r"(a[1]), "r"(a[2]), "r"(a[3]), "r"(b[0]), "r"(b[1]));
}
static __device__ __forceinline__ void mma_bf16_k8(float* c, const unsigned* a, unsigned b) {
    asm volatile("mma.sync.aligned.m16n8k8.row.col.f32.bf16.bf16.f32 "
        "{%0,%1,%2,%3},{%4,%5},{%6},{%0,%1,%2,%3};\n"
        : "+f"(c[0]), "+f"(c[1]), "+f"(c[2]), "+f"(c[3])
        : "r"(a[0]), "r"(a[1]), "r"(b));
}
#define LDB2(bq, addr) asm volatile( \
    "ldmatrix.sync.aligned.m8n8.x2.trans.shared.b16 {%0,%1},[%2];" \
    : "=r"((bq)[0]), "=r"((bq)[1]) : "r"(addr))
#define LDB1(b, addr) asm volatile( \
    "ldmatrix.sync.aligned.m8n8.x1.trans.shared.b16 {%0},[%1];" \
    : "=r"(b) : "r"(addr))
#define LDA4(aq, addr) asm volatile( \
    "ldmatrix.sync.aligned.m8n8.x4.shared.b16 {%0,%1,%2,%3},[%4];" \
    : "=r"((aq)[0]), "=r"((aq)[1]), "=r"((aq)[2]), "=r"((aq)[3]) : "r"(addr))
#define LDA2(aq, addr) asm volatile( \
    "ldmatrix.sync.aligned.m8n8.x2.shared.b16 {%0,%1},[%2];" \
    : "=r"((aq)[0]), "=r"((aq)[1]) : "r"(addr))

#define SM_STRIDE 72

#define CPA(dst, src, sz) asm volatile( \
    "cp.async.cg.shared.global [%0], [%1], 16, %2;" :: "r"(dst), "l"(src), "r"(sz))
#define CPA_COMMIT() asm volatile("cp.async.commit_group;")
template<int N>
static __device__ __forceinline__ void cpa_wait() {
    asm volatile("cp.async.wait_group %0;" :: "n"(N));
}

// MTx16(M) x 64(N) x KSN*16(K), 3-pass split; A via ldmatrix.x4
template<int MT, int KSN, int AS, int BS>
static __device__ __forceinline__ void mma_stageG(float (*acc)[4][4],
        const bf16* Ah, const bf16* Al, const bf16* Bh, const bf16* Bl,
        int wm0, int wn0) {
    int lane = threadIdx.x & 31;
    int arow = lane & 15;
    int acol = (lane >> 4) * 8;
    #pragma unroll
    for (int kk = 0; kk < KSN; kk++) {
        int kb = kk*16;
        unsigned aH[MT][4], aL[MT][4], bH[4][2], bL[4][2];
        #pragma unroll
        for (int mt = 0; mt < MT; mt++) {
            int r = wm0 + mt*16 + arow;
            LDA4(aH[mt], sptr(Ah + r*AS + kb + acol));
            LDA4(aL[mt], sptr(Al + r*AS + kb + acol));
        }
        int rr = kb + (lane & 15);
        #pragma unroll
        for (int nt = 0; nt < 4; nt++) {
            LDB2(bH[nt], sptr(Bh + rr*BS + wn0 + nt*8));
            LDB2(bL[nt], sptr(Bl + rr*BS + wn0 + nt*8));
        }
        #pragma unroll
        for (int mt = 0; mt < MT; mt++)
            #pragma unroll
            for (int nt = 0; nt < 4; nt++) {
                mma_bf16(acc[mt][nt], aH[mt], bH[nt]);
                mma_bf16(acc[mt][nt], aH[mt], bL[nt]);
                mma_bf16(acc[mt][nt], aL[mt], bH[nt]);
            }
    }
}

// ---------------- fused left: Y1 = A@X, Y2 = 2*A@Y1 - X ---------------------
// grid (100, 8), 256 threads. Warp-private A pipeline, 3 block barriers total.
// Warp = 32 M-rows x 64 N-cols (MT=2, NT=8). 13 K chunks (12 x k16 + k8).
#define LXB_H 0
#define LXB_L 36864
#define LY1_H 73728
#define LY1_L 110592
#define LAP   147456                       // per-warp: Ah0,Ah1,Al (1536 B each)
#define LEFT_SMEM 184320

__global__ __launch_bounds__(256) void k_leftfused() {
    extern __shared__ __align__(128) char smem[];
    unsigned sb = sptr(smem);
    int n0 = blockIdx.x*64, b = blockIdx.y;
    int tid = threadIdx.x;
    int lane = tid & 31, warp = tid >> 5;
    int g = lane >> 2, tig = lane & 3;

    const bf16* XBh = (const bf16*)(smem + LXB_H);
    const bf16* XBl = (const bf16*)(smem + LXB_L);
    bf16* Y1h = (bf16*)(smem + LY1_H);
    bf16* Y1l = (bf16*)(smem + LY1_L);

    unsigned PAW = sb + LAP + warp*4608;

    // warp-private A chunk load: rows warp*32..+31, k cols c*16..+15 (c<12) or 192..199
    auto issueA = [&](int c, int isL) {
        unsigned dst = PAW + (isL ? 3072 : (c & 1)*1536);
        const bf16* base = isL ? gA_l : gA_h;
        if (c < 12) {
            #pragma unroll
            for (int i = 0; i < 2; i++) {
                int idx = lane + i*32, r = idx >> 1, s = idx & 1;
                CPA(dst + r*48 + s*16, base + (size_t)(warp*32 + r)*NP + c*16 + s*8, 16);
            }
        } else {
            CPA(dst + lane*48, base + (size_t)(warp*32 + lane)*NP + 192, 16);
        }
        CPA_COMMIT();
    };

    // one K-chunk of MMA (warp-private A, shared B)
    auto chunkH = [&](int c, const bf16* Ah, const bf16* Bh, const bf16* Bl, float (*acc)[4]) {
        if (c < 12) {
            unsigned a4[2][4];
            #pragma unroll
            for (int mt = 0; mt < 2; mt++)
                LDA4(a4[mt], sptr(Ah + ((lane & 15) + mt*16)*24 + (lane >> 4)*8));
            int rr = c*16 + (lane & 15);
            #pragma unroll
            for (int nt = 0; nt < 8; nt++) {
                unsigned bh[2], bl[2];
                LDB2(bh, sptr(Bh + rr*SM_STRIDE + nt*8));
                LDB2(bl, sptr(Bl + rr*SM_STRIDE + nt*8));
                #pragma unroll
                for (int mt = 0; mt < 2; mt++) {
                    mma_bf16(acc[mt*8 + nt], a4[mt], bh);
                    mma_bf16(acc[mt*8 + nt], a4[mt], bl);
                }
            }
        } else {
            unsigned a2[2][2];
            #pragma unroll
            for (int mt = 0; mt < 2; mt++)
                LDA2(a2[mt], sptr(Ah + ((lane & 15) + mt*16)*24));
            int rr = 192 + (lane & 7);
            #pragma unroll
            for (int nt = 0; nt < 8; nt++) {
                unsigned bh, bl;
                LDB1(bh, sptr(Bh + rr*SM_STRIDE + nt*8));
                LDB1(bl, sptr(Bl + rr*SM_STRIDE + nt*8));
                #pragma unroll
                for (int mt = 0; mt < 2; mt++) {
                    mma_bf16_k8(acc[mt*8 + nt], a2[mt], bh);
                    mma_bf16_k8(acc[mt*8 + nt], a2[mt], bl);
                }
            }
        }
    };
    auto chunkL = [&](int c, const bf16* Al, const bf16* Bh, float (*acc)[4]) {
        if (c < 12) {
            unsigned a4[2][4];
            #pragma unroll
            for (int mt = 0; mt < 2; mt++)
                LDA4(a4[mt], sptr(Al + ((lane & 15) + mt*16)*24 + (lane >> 4)*8));
            int rr = c*16 + (lane & 15);
            #pragma unroll
            for (int nt = 0; nt < 8; nt++) {
                unsigned bh[2];
                LDB2(bh, sptr(Bh + rr*SM_STRIDE + nt*8));
                #pragma unroll
                for (int mt = 0; mt < 2; mt++)
                    mma_bf16(acc[mt*8 + nt], a4[mt], bh);
            }
        } else {
            unsigned a2[2][2];
            #pragma unroll
            for (int mt = 0; mt < 2; mt++)
                LDA2(a2[mt], sptr(Al + ((lane & 15) + mt*16)*24));
            int rr = 192 + (lane & 7);
            #pragma unroll
            for (int nt = 0; nt < 8; nt++) {
                unsigned bh;
                LDB1(bh, sptr(Bh + rr*SM_STRIDE + nt*8));
                #pragma unroll
                for (int mt = 0; mt < 2; mt++)
                    mma_bf16_k8(acc[mt*8 + nt], a2[mt], bh);
            }
        }
    };

    // run one full GEMM stage: acc += Ab @ Bsrc  (warp-private pipeline)
    auto gemm_stage = [&](const bf16* Bh, const bf16* Bl, float (*acc)[4]) {
        #pragma unroll 1
        for (int c = 0; c < 13; c++) {
            const bf16* Ah = (const bf16*)(smem + LAP + warp*4608 + (c & 1)*1536);
            const bf16* Al = (const bf16*)(smem + LAP + warp*4608 + 3072);
            if (c == 12) cpa_wait<1>(); else cpa_wait<2>();
            __syncwarp();
            chunkH(c, Ah, Bh, Bl, acc);
            if (c == 12) cpa_wait<0>(); else cpa_wait<1>();
            __syncwarp();
            chunkL(c, Al, Bh, acc);
            if (c < 12) { issueA(c+1, 1); if (c < 11) issueA(c+2, 0); }
        }
    };

    // ---- load X block + prologue ----
    #pragma unroll
    for (int i = 0; i < 16; i++) {
        int u = tid + i*256;
        int hl = u >> 11, rem = u & 2047;
        int r = rem >> 3, s = rem & 7;
        const bf16* src = (hl ? gX_l : gX_h) + ((size_t)b*NP + r)*NCH + n0 + s*8;
        CPA(sb + (hl ? LXB_L : LXB_H) + r*144 + s*16, src, 16);
    }
    CPA_COMMIT();
    issueA(0, 0); issueA(0, 1); issueA(1, 0);
    cpa_wait<3>();          // X group done (A groups may still be in flight)
    __syncthreads();        // X visible block-wide

    float acc[16][4];
    #pragma unroll
    for (int i = 0; i < 16; i++) for (int r = 0; r < 4; r++) acc[i][r] = 0.f;

    // ---- stage 1: Y1 = A @ X ----
    gemm_stage(XBh, XBl, acc);

    // epilogue 1: Y1 -> smem (own rows) + global
    #pragma unroll
    for (int mt = 0; mt < 2; mt++)
        #pragma unroll
        for (int nt = 0; nt < 8; nt++) {
            int col = nt*8 + tig*2;
            #pragma unroll
            for (int rh = 0; rh < 2; rh++) {
                int row = warp*32 + mt*16 + g + rh*8;
                float v0 = acc[mt*8 + nt][rh*2+0], v1 = acc[mt*8 + nt][rh*2+1];
                bf16 h0 = __float2bfloat16(v0), h1 = __float2bfloat16(v1);
                bf16 l0 = __float2bfloat16(v0 - __bfloat162float(h0));
                bf16 l1 = __float2bfloat16(v1 - __bfloat162float(h1));
                bf162 ph; ph.x = h0; ph.y = h1;
                bf162 pl; pl.x = l0; pl.y = l1;
                *(bf162*)(Y1h + row*SM_STRIDE + col) = ph;
                *(bf162*)(Y1l + row*SM_STRIDE + col) = pl;
                if (row < Nn) {
                    size_t di = ((size_t)b*NP + row)*NCH + n0 + col;
                    *(unsigned*)(gY1_h + di) = *reinterpret_cast<unsigned*>(&ph);
                    *(unsigned*)(gY1_l + di) = *reinterpret_cast<unsigned*>(&pl);
                }
            }
        }

    issueA(0, 0); issueA(0, 1); issueA(1, 0);   // stage-2 prologue (overlaps barrier)
    __syncthreads();                             // Y1 visible block-wide

    #pragma unroll
    for (int i = 0; i < 16; i++) for (int r = 0; r < 4; r++) acc[i][r] = 0.f;

    // ---- stage 2: Y2 = 2*A @ Y1 - X ----
    gemm_stage(Y1h, Y1l, acc);

    // epilogue 2
    #pragma unroll
    for (int mt = 0; mt < 2; mt++)
        #pragma unroll
        for (int nt = 0; nt < 8; nt++) {
            int col = nt*8 + tig*2;
            #pragma unroll
            for (int rh = 0; rh < 2; rh++) {
                int row = warp*32 + mt*16 + g + rh*8;
                if (row < Nn) {
                    int xo = row*SM_STRIDE + col;
                    float x0 = __bfloat162float(XBh[xo])   + __bfloat162float(XBl[xo]);
                    float x1 = __bfloat162float(XBh[xo+1]) + __bfloat162float(XBl[xo+1]);
                    float v0 = 2.f*acc[mt*8 + nt][rh*2+0] - x0;
                    float v1 = 2.f*acc[mt*8 + nt][rh*2+1] - x1;
                    bf16 h0 = __float2bfloat16(v0), h1 = __float2bfloat16(v1);
                    bf16 l0 = __float2bfloat16(v0 - __bfloat162float(h0));
                    bf16 l1 = __float2bfloat16(v1 - __bfloat162float(h1));
                    bf162 ph; ph.x = h0; ph.y = h1;
                    bf162 pl; pl.x = l0; pl.y = l1;
                    size_t di = ((size_t)b*NP + row)*NCH + n0 + col;
                    *(unsigned*)(gY2_h + di) = *reinterpret_cast<unsigned*>(&ph);
                    *(unsigned*)(gY2_l + di) = *reinterpret_cast<unsigned*>(&pl);
                }
            }
        }
}

// ---------------- fused mix+right, 256 threads ------------------------------
#define GSTR     200
#define OFF_GH   0
#define OFF_GL   80000
#define OFF_POOL 160000
#define P1_S(hl)     (OFF_POOL + (hl)*13312)                 // 64 x 104 bf16
#define P1_W(buf,hl) (OFF_POOL + 26624 + (buf)*13824 + (hl)*6912)  // 48 x 72 bf16
#define FUSED_SMEM   228096

__global__ __launch_bounds__(256) void k_fused(const float* __restrict__ bias,
                                               float* __restrict__ out) {
    extern __shared__ __align__(128) char smem[];
    unsigned sb = sptr(smem);
    int bi = blockIdx.x;
    int bb = bi / Nn, ii = bi % Nn;
    size_t abase = ((size_t)(bb*NP + ii))*NCH;
    int tid = threadIdx.x;
    int lane = tid & 31, warp = tid >> 5;
    int g = lane >> 2, tig = lane & 3;

    bf16* Ghp = (bf16*)(smem + OFF_GH);
    bf16* Glp = (bf16*)(smem + OFF_GL);

    auto loadW = [&](int st, int buf) {
        int nt3 = st >> 1, half = st & 1;
        #pragma unroll
        for (int i = 0; i < 3; i++) {
            int u = tid + i*256;
            int hl = u / 384, rem = u % 384;
            int r = rem >> 3, s = rem & 7;
            const bf16* wsrc = (hl ? gW_l : gW_h) + (size_t)(half*48 + r)*GW + nt3*64 + s*8;
            CPA(sb + P1_W(buf,hl) + r*144 + s*16, wsrc, 16);
        }
        CPA_COMMIT();
    };

    int p1m0 = (warp >> 1)*16, p1n0 = (warp & 1)*32;

    // ---- phase 1: build G in smem ----
    for (int qp = 0; qp < 4; qp++) {
        int q0 = qp*64;
        __syncthreads();
        #pragma unroll
        for (int i = 0; i < 3; i++) {
            int u = tid + i*256;
            int r = u / 12, s = u % 12;
            int q = q0 + r;
            int seg = s >> 2, cc = (s & 3)*8;
            int sz = (q < Nn) ? 16 : 0;
            int qq = (q < Nn) ? q : 0;
            size_t off = abase + (size_t)qq*32 + cc;
            const bf16 *ph, *pl;
            if (seg == 0)      { ph = gX_h  + off; pl = gX_l  + off; }
            else if (seg == 1) { ph = gY1_h + off; pl = gY1_l + off; }
            else               { ph = gY2_h + off; pl = gY2_l + off; }
            unsigned d = r*208 + s*16;
            CPA(sb + P1_S(0) + d, ph, sz);
            CPA(sb + P1_S(1) + d, pl, sz);
        }
        loadW(0, 0);
        loadW(1, 1);

        const bf16* Sh = (const bf16*)(smem + P1_S(0));
        const bf16* Sl = (const bf16*)(smem + P1_S(1));

        float acc1[1][4][4];
        #pragma unroll
        for (int st = 0; st < 6; st++) {
            if (st < 5) cpa_wait<1>(); else cpa_wait<0>();
            __syncthreads();
            if (st < 4) loadW(st+2, (st+2)%3);
            int nt3 = st >> 1, half = st & 1;
            const bf16* Wh = (const bf16*)(smem + P1_W(st%3,0));
            const bf16* Wl = (const bf16*)(smem + P1_W(st%3,1));
            if (half == 0) {
                #pragma unroll
                for (int j = 0; j < 4; j++) for (int r = 0; r < 4; r++) acc1[0][j][r] = 0.f;
            }
            mma_stageG<1,3,104,SM_STRIDE>(acc1, Sh + half*48, Sl + half*48, Wh, Wl, p1m0, p1n0);
            if (half == 1) {
                #pragma unroll
                for (int nt = 0; nt < 4; nt++) {
                    int col = nt3*64 + p1n0 + nt*8 + tig*2;
                    #pragma unroll
                    for (int rh = 0; rh < 2; rh++) {
                        int row = q0 + p1m0 + g + rh*8;
                        if (row < Nn) {
                            float v0 = acc1[0][nt][rh*2+0], v1 = acc1[0][nt][rh*2+1];
                            bf16 h0 = __float2bfloat16(v0), h1 = __float2bfloat16(v1);
                            bf16 l0 = __float2bfloat16(v0 - __bfloat162float(h0));
                            bf16 l1 = __float2bfloat16(v1 - __bfloat162float(h1));
                            bf162 ph; ph.x = h0; ph.y = h1;
                            bf162 pl; pl.x = l0; pl.y = l1;
                            *(bf162*)(Ghp + row*GSTR + col) = ph;
                            *(bf162*)(Glp + row*GSTR + col) = pl;
                        }
                    }
                }
            }
        }
    }

    __syncthreads();   // G complete; no block barriers below

    // ---- phase 2: warp-private A pipeline, 128-row j-tiles ----
    unsigned PA = sb + OFF_POOL + warp*6912;

    for (int jt = 0; jt < 2; jt++) {
        int jr = jt*128 + warp*16;
        float acc[8][4];
        #pragma unroll
        for (int j = 0; j < 8; j++) for (int r = 0; r < 4; r++) acc[j][r] = 0.f;

        auto issueA = [&](int c, int isL) {
            int phse = c >> 2, kc = c & 3;
            const bf16* src = isL ? (phse ? gR2_l : gRt_l) : (phse ? gR2_h : gRt_h);
            unsigned dst = PA + (isL ? 4608 : (c & 1)*2304);
            if (kc < 3) {
                int kq = kc*64;
                #pragma unroll
                for (int i = 0; i < 4; i++) {
                    int idx = lane + i*32, r = idx >> 3, s = idx & 7;
                    CPA(dst + r*144 + s*16, src + (size_t)(jr + r)*NP + kq + s*8, 16);
                }
            } else {
                if (lane < 16) CPA(dst + lane*144, src + (size_t)(jr + lane)*NP + 192, 16);
            }
            CPA_COMMIT();
        };

        issueA(0, 0); issueA(0, 1); issueA(1, 0);

        #pragma unroll
        for (int c = 0; c < 8; c++) {
            int phse = c >> 2, kc = c & 3;
            int coff = phse ? 128 : 64;
            const bf16* Ah = (const bf16*)(smem + OFF_POOL + warp*6912 + (c & 1)*2304);
            const bf16* Al = (const bf16*)(smem + OFF_POOL + warp*6912 + 4608);

            if (c == 7) cpa_wait<1>(); else cpa_wait<2>();
            __syncwarp();
            if (kc < 3) {
                #pragma unroll
                for (int ks = 0; ks < 4; ks++) {
                    unsigned a4[4];
                    LDA4(a4, sptr(Ah + (lane & 15)*72 + ks*16 + (lane >> 4)*8));
                    int rr = kc*64 + ks*16 + (lane & 15);
                    #pragma unroll
                    for (int nt = 0; nt < 8; nt++) {
                        unsigned bh[2], bl[2];
                        LDB2(bh, sptr(Ghp + rr*GSTR + coff + nt*8));
                        LDB2(bl, sptr(Glp + rr*GSTR + coff + nt*8));
                        mma_bf16(acc[nt], a4, bh);
                        mma_bf16(acc[nt], a4, bl);
                    }
                }
            } else {
                unsigned a2[2];
                LDA2(a2, sptr(Ah + (lane & 15)*72));
                int rr = 192 + (lane & 7);
                #pragma unroll
                for (int nt = 0; nt < 8; nt++) {
                    unsigned bh, bl;
                    LDB1(bh, sptr(Ghp + rr*GSTR + coff + nt*8));
                    LDB1(bl, sptr(Glp + rr*GSTR + coff + nt*8));
                    mma_bf16_k8(acc[nt], a2, bh);
                    mma_bf16_k8(acc[nt], a2, bl);
                }
            }

            if (c == 7) cpa_wait<0>(); else cpa_wait<1>();
            __syncwarp();
            if (kc < 3) {
                #pragma unroll
                for (int ks = 0; ks < 4; ks++) {
                    unsigned a4[4];
                    LDA4(a4, sptr(Al + (lane & 15)*72 + ks*16 + (lane >> 4)*8));
                    int rr = kc*64 + ks*16 + (lane & 15);
                    #pragma unroll
                    for (int nt = 0; nt < 8; nt++) {
                        unsigned bh[2];
                        LDB2(bh, sptr(Ghp + rr*GSTR + coff + nt*8));
                        mma_bf16(acc[nt], a4, bh);
                    }
                }
            } else {
                unsigned a2[2];
                LDA2(a2, sptr(Al + (lane & 15)*72));
                int rr = 192 + (lane & 7);
                #pragma unroll
                for (int nt = 0; nt < 8; nt++) {
                    unsigned bh;
                    LDB1(bh, sptr(Ghp + rr*GSTR + coff + nt*8));
                    mma_bf16_k8(acc[nt], a2, bh);
                }
            }
            if (c < 7) { issueA(c+1, 1); if (c < 6) issueA(c+2, 0); }
        }

        #pragma unroll
        for (int nt = 0; nt < 8; nt++) {
            int o = nt*8 + tig*2;
            #pragma unroll
            for (int rh = 0; rh < 2; rh++) {
                int j = jr + g + rh*8;
                if (j < Nn) {
                    float v0 = acc[nt][rh*2+0], v1 = acc[nt][rh*2+1];
                    int gr = j*GSTR;
                    float g0a = __bfloat162float(Ghp[gr + o])       + __bfloat162float(Glp[gr + o]);
                    float g0b = __bfloat162float(Ghp[gr + o + 1])   + __bfloat162float(Glp[gr + o + 1]);
                    float g2a = __bfloat162float(Ghp[gr + 128 + o]) + __bfloat162float(Glp[gr + 128 + o]);
                    float g2b = __bfloat162float(Ghp[gr + 128 + o + 1]) + __bfloat162float(Glp[gr + 128 + o + 1]);
                    size_t oi = ((size_t)bi*Nn + j)*64 + o;
                    out[oi]     = bias[o]     + g0a - g2a + v0;
                    out[oi + 1] = bias[o + 1] + g0b - g2b + v1;
                }
            }
        }
    }
}

// ---------------------------------------------------------------------------
extern "C" void kernel_launch(void* const* d_in, const int* in_sizes, int n_in,
                              void* d_out, int out_size) {
    const float* x    = (const float*)d_in[0];
    const float* adj  = (const float*)d_in[1];
    const float* w    = (const float*)d_in[2];
    const float* bias = (const float*)d_in[3];
    float* out = (float*)d_out;

    cudaFuncSetAttribute(k_leftfused, cudaFuncAttributeMaxDynamicSharedMemorySize, LEFT_SMEM);
    cudaFuncSetAttribute(k_fused,     cudaFuncAttributeMaxDynamicSharedMemorySize, FUSED_SMEM);

    k_deg<<<1, 256>>>(adj);
    k_buildA<<<(NP*NP + 255)/256, 256>>>(adj);
    k_R2<<<dim3(16, 16), dim3(16, 16)>>>();
    k_prepsplit<<<768 + 12800 + 96, 256>>>(x, w);

    k_leftfused<<<dim3(100, Bx), 256, LEFT_SMEM>>>();
    k_fused<<<1600, 256, FUSED_SMEM>>>(bias, out);
}

// round 15
// speedup vs baseline: 1.5317x; 1.5317x over previous
#include <cuda_runtime.h>
#include <cuda_bf16.h>
#include <cstdint>

#define Nn   200
#define NP   256
#define Bx   8
#define NCH  6400
#define GW   192

typedef __nv_bfloat16 bf16;
typedef __nv_bfloat162 bf162;

// ---------------- static scratch ----------------
__device__ float g_d0[NP];
__device__ float g_d1[NP];
__device__ float g_Afp[NP*NP];
__device__ float g_Rtf[NP*NP];
__device__ float g_R2f[NP*NP];
__device__ bf16  gA_h[NP*NP],  gA_l[NP*NP];
__device__ bf16  gRt_h[NP*NP], gRt_l[NP*NP];
__device__ bf16  gR2_h[NP*NP], gR2_l[NP*NP];
__device__ bf16  gX_h[(size_t)Bx*NP*NCH],  gX_l[(size_t)Bx*NP*NCH];
__device__ bf16  gY1_h[(size_t)Bx*NP*NCH], gY1_l[(size_t)Bx*NP*NCH];
__device__ bf16  gY2_h[(size_t)Bx*NP*NCH], gY2_l[(size_t)Bx*NP*NCH];
__device__ bf16  gW_h[128*GW], gW_l[128*GW];            // [k=128][n=192]

// ---------------- prep kernels ----------------
// parallel degree sums: one block per node i, smem tree reduction
__global__ void k_deg(const float* __restrict__ adj) {
    int i = blockIdx.x;
    int tid = threadIdx.x;
    float cs = 0.f, rs = 0.f;
    if (tid < Nn && tid != i) {
        cs = adj[tid*Nn + i];
        rs = adj[i*Nn + tid];
    }
    __shared__ float scs[256], srs[256];
    scs[tid] = cs; srs[tid] = rs;
    __syncthreads();
    #pragma unroll
    for (int s = 128; s > 0; s >>= 1) {
        if (tid < s) { scs[tid] += scs[tid+s]; srs[tid] += srs[tid+s]; }
        __syncthreads();
    }
    if (tid == 0) {
        g_d0[i] = (scs[0] > 0.f) ? rsqrtf(scs[0]) : 0.f;
        g_d1[i] = (srs[0] > 0.f) ? rsqrtf(srs[0]) : 0.f;
    }
}
__global__ void k_buildA(const float* __restrict__ adj) {
    int idx = blockIdx.x * blockDim.x + threadIdx.x;
    if (idx < NP*NP) {
        int e = idx / NP, b = idx % NP;
        float v = 0.f;
        if (e < Nn && b < Nn && e != b) v = g_d0[b] * adj[b*Nn + e] * g_d1[e];
        g_Afp[e*NP + b] = v;
        g_Rtf[b*NP + e] = v;
    }
}
__global__ void k_R2() {
    __shared__ float a[16][17], b[16][17];
    int tx = threadIdx.x, ty = threadIdx.y;
    int j = blockIdx.y*16 + ty, q = blockIdx.x*16 + tx;
    float s = 0.f;
    for (int p0 = 0; p0 < NP; p0 += 16) {
        a[ty][tx] = g_Rtf[j*NP + p0 + tx];
        b[ty][tx] = g_Rtf[(p0+ty)*NP + q];
        __syncthreads();
        #pragma unroll
        for (int p = 0; p < 16; p++) s += a[ty][p]*b[p][tx];
        __syncthreads();
    }
    g_R2f[j*NP + q] = 2.f*s;
}
static __device__ __forceinline__ unsigned pack2(float a, float b) {
    bf162 t; t.x = __float2bfloat16(a); t.y = __float2bfloat16(b);
    return *reinterpret_cast<unsigned*>(&t);
}
__global__ void k_prepsplit(const float* __restrict__ x, const float* __restrict__ w) {
    int b = blockIdx.x;
    int tid = threadIdx.x;
    if (b < 768) {
        int which = b / 256;
        const float* s; bf16 *h, *l;
        if (which == 0)      { s = g_Afp; h = gA_h;  l = gA_l;  }
        else if (which == 1) { s = g_Rtf; h = gRt_h; l = gRt_l; }
        else                 { s = g_R2f; h = gR2_h; l = gR2_l; }
        int i = (b % 256)*256 + tid;
        float v = s[i];
        bf16 hh = __float2bfloat16(v);
        h[i] = hh;
        l[i] = __float2bfloat16(v - __bfloat162float(hh));
    } else if (b < 768 + 12800) {
        size_t i4 = ((size_t)(b - 768)*256 + tid) * 4;
        int col = (int)(i4 % NCH);
        int r   = (int)((i4 / NCH) % NP);
        int bb  = (int)(i4 / ((size_t)NP*NCH));
        float v0 = 0.f, v1 = 0.f, v2 = 0.f, v3 = 0.f;
        if (r < Nn) {
            const float4 xv = *reinterpret_cast<const float4*>(x + ((size_t)bb*Nn + r)*NCH + col);
            v0 = xv.x; v1 = xv.y; v2 = xv.z; v3 = xv.w;
        }
        bf16 h0 = __float2bfloat16(v0), h1 = __float2bfloat16(v1);
        bf16 h2 = __float2bfloat16(v2), h3 = __float2bfloat16(v3);
        float l0 = v0 - __bfloat162float(h0), l1 = v1 - __bfloat162float(h1);
        float l2 = v2 - __bfloat162float(h2), l3 = v3 - __bfloat162float(h3);
        bf162 ph0; ph0.x = h0; ph0.y = h1;
        bf162 ph1; ph1.x = h2; ph1.y = h3;
        uint2 hv = make_uint2(*reinterpret_cast<unsigned*>(&ph0), *reinterpret_cast<unsigned*>(&ph1));
        uint2 lv = make_uint2(pack2(l0, l1), pack2(l2, l3));
        *reinterpret_cast<uint2*>(gX_h + i4) = hv;
        *reinterpret_cast<uint2*>(gX_l + i4) = lv;
    } else {
        int i = (b - 768 - 12800)*256 + tid;
        int k = i / GW, n = i % GW;
        float v = 0.f;
        if (k < 96) {
            int k1 = k / 32, c = k & 31;
            int k2 = n / 64, o = n & 63;
            v = w[o*288 + (k1*3 + k2)*32 + c];
        }
        bf16 hh = __float2bfloat16(v);
        gW_h[i] = hh;
        gW_l[i] = __float2bfloat16(v - __bfloat162float(hh));
    }
}

// ---------------- mma/async helpers ----------------
static __device__ __forceinline__ unsigned sptr(const void* p) {
    return (unsigned)__cvta_generic_to_shared(p);
}
static __device__ __forceinline__ void mma_bf16(float* c, const unsigned* a, const unsigned* b) {
    asm volatile("mma.sync.aligned.m16n8k16.row.col.f32.bf16.bf16.f32 "
        "{%0,%1,%2,%3},{%4,%5,%6,%7},{%8,%9},{%0,%1,%2,%3};\n"
        : "+f"(c[0]), "+f"(c[1]), "+f"(c[2]), "+f"(c[3])
        : "r"(a[0]), "r"(a[1]), "r"(a[2]), "r"(a[3]), "r"(b[0]), "r"(b[1]));
}
static __device__ __forceinline__ void mma_bf16_k8(float* c, const unsigned* a, unsigned b) {
    asm volatile("mma.sync.aligned.m16n8k8.row.col.f32.bf16.bf16.f32 "
        "{%0,%1,%2,%3},{%4,%5},{%6},{%0,%1,%2,%3};\n"
        : "+f"(c[0]), "+f"(c[1]), "+f"(c[2]), "+f"(c[3])
        : "r"(a[0]), "r"(a[1]), "r"(b));
}
#define LDB2(bq, addr) asm volatile( \
    "ldmatrix.sync.aligned.m8n8.x2.trans.shared.b16 {%0,%1},[%2];" \
    : "=r"((bq)[0]), "=r"((bq)[1]) : "r"(addr))
#define LDB1(b, addr) asm volatile( \
    "ldmatrix.sync.aligned.m8n8.x1.trans.shared.b16 {%0},[%1];" \
    : "=r"(b) : "r"(addr))
#define LDA4(aq, addr) asm volatile( \
    "ldmatrix.sync.aligned.m8n8.x4.shared.b16 {%0,%1,%2,%3},[%4];" \
    : "=r"((aq)[0]), "=r"((aq)[1]), "=r"((aq)[2]), "=r"((aq)[3]) : "r"(addr))
#define LDA2(aq, addr) asm volatile( \
    "ldmatrix.sync.aligned.m8n8.x2.shared.b16 {%0,%1},[%2];" \
    : "=r"((aq)[0]), "=r"((aq)[1]) : "r"(addr))

#define SM_STRIDE 72

#define CPA(dst, src, sz) asm volatile( \
    "cp.async.cg.shared.global [%0], [%1], 16, %2;" :: "r"(dst), "l"(src), "r"(sz))
#define CPA_COMMIT() asm volatile("cp.async.commit_group;")
template<int N>
static __device__ __forceinline__ void cpa_wait() {
    asm volatile("cp.async.wait_group %0;" :: "n"(N));
}

// MTx16(M) x 64(N) x KSN*16(K), 3-pass split; A via ldmatrix.x4
template<int MT, int KSN, int AS, int BS>
static __device__ __forceinline__ void mma_stageG(float (*acc)[4][4],
        const bf16* Ah, const bf16* Al, const bf16* Bh, const bf16* Bl,
        int wm0, int wn0) {
    int lane = threadIdx.x & 31;
    int arow = lane & 15;
    int acol = (lane >> 4) * 8;
    #pragma unroll
    for (int kk = 0; kk < KSN; kk++) {
        int kb = kk*16;
        unsigned aH[MT][4], aL[MT][4], bH[4][2], bL[4][2];
        #pragma unroll
        for (int mt = 0; mt < MT; mt++) {
            int r = wm0 + mt*16 + arow;
            LDA4(aH[mt], sptr(Ah + r*AS + kb + acol));
            LDA4(aL[mt], sptr(Al + r*AS + kb + acol));
        }
        int rr = kb + (lane & 15);
        #pragma unroll
        for (int nt = 0; nt < 4; nt++) {
            LDB2(bH[nt], sptr(Bh + rr*BS + wn0 + nt*8));
            LDB2(bL[nt], sptr(Bl + rr*BS + wn0 + nt*8));
        }
        #pragma unroll
        for (int mt = 0; mt < MT; mt++)
            #pragma unroll
            for (int nt = 0; nt < 4; nt++) {
                mma_bf16(acc[mt][nt], aH[mt], bH[nt]);
                mma_bf16(acc[mt][nt], aH[mt], bL[nt]);
                mma_bf16(acc[mt][nt], aL[mt], bH[nt]);
            }
    }
}

// single k8 step (3-pass)
template<int MT, int AS, int BS>
static __device__ __forceinline__ void mma_k8stage(float (*acc)[4][4],
        const bf16* Ah, const bf16* Al, const bf16* Bh, const bf16* Bl,
        int wm0, int wn0) {
    int lane = threadIdx.x & 31;
    int arow = lane & 15;
    unsigned aH[MT][2], aL[MT][2], bH[4], bL[4];
    #pragma unroll
    for (int mt = 0; mt < MT; mt++) {
        int r = wm0 + mt*16 + arow;
        LDA2(aH[mt], sptr(Ah + r*AS));
        LDA2(aL[mt], sptr(Al + r*AS));
    }
    int rr = lane & 7;
    #pragma unroll
    for (int nt = 0; nt < 4; nt++) {
        LDB1(bH[nt], sptr(Bh + rr*BS + wn0 + nt*8));
        LDB1(bL[nt], sptr(Bl + rr*BS + wn0 + nt*8));
    }
    #pragma unroll
    for (int mt = 0; mt < MT; mt++)
        #pragma unroll
        for (int nt = 0; nt < 4; nt++) {
            mma_bf16_k8(acc[mt][nt], aH[mt], bH[nt]);
            mma_bf16_k8(acc[mt][nt], aH[mt], bL[nt]);
            mma_bf16_k8(acc[mt][nt], aL[mt], bH[nt]);
        }
}

// ---------------- fused left: Y1 = A@X, Y2 = 2*A@Y1 - X (one kernel) --------
#define XB_H   0
#define XB_L   36864
#define Y1S_H  73728
#define Y1S_L  110592
#define LA(st,hl) (147456 + (st)*40960 + (hl)*20480)   // 256 x 32 bf16, stride 40
#define LEFT_SMEM 229376

__global__ __launch_bounds__(256) void k_leftfused() {
    extern __shared__ __align__(128) char smem[];
    unsigned sb = sptr(smem);
    int n0 = blockIdx.x*64, b = blockIdx.y;
    int tid = threadIdx.x;
    int lane = tid & 31, warp = tid >> 5;
    int g = lane >> 2, tig = lane & 3;
    int wm0 = (warp >> 1)*64, wn0 = (warp & 1)*32;

    const bf16* XBh = (const bf16*)(smem + XB_H);
    const bf16* XBl = (const bf16*)(smem + XB_L);
    bf16* Y1h = (bf16*)(smem + Y1S_H);
    bf16* Y1l = (bf16*)(smem + Y1S_L);

    auto loadA = [&](int c, int st) {
        int k0 = c*32;
        #pragma unroll
        for (int i = 0; i < 8; i++) {
            int u = tid + i*256;
            int hl = u >> 10, rem = u & 1023;
            int r = rem >> 2, s = rem & 3;
            const bf16* src = (hl ? gA_l : gA_h) + (size_t)r*NP + k0 + s*8;
            CPA(sb + LA(st,hl) + r*80 + s*16, src, 16);
        }
        CPA_COMMIT();
    };

    #pragma unroll
    for (int i = 0; i < 16; i++) {
        int u = tid + i*256;
        int hl = u >> 11, rem = u & 2047;
        int r = rem >> 3, s = rem & 7;
        const bf16* src = (hl ? gX_l : gX_h) + ((size_t)b*NP + r)*NCH + n0 + s*8;
        CPA(sb + (hl ? XB_L : XB_H) + r*144 + s*16, src, 16);
    }
    loadA(0, 0);

    float acc[4][4][4];
    #pragma unroll
    for (int i = 0; i < 4; i++) for (int j = 0; j < 4; j++) for (int r = 0; r < 4; r++) acc[i][j][r] = 0.f;

    #pragma unroll
    for (int c = 0; c < 7; c++) {
        cpa_wait<0>();
        __syncthreads();
        if (c < 6) loadA(c+1, (c+1)&1);
        const bf16* Ah = (const bf16*)(smem + LA(c&1,0));
        const bf16* Al = (const bf16*)(smem + LA(c&1,1));
        if (c == 6) mma_k8stage<4,40,SM_STRIDE>(acc, Ah, Al, XBh + 192*SM_STRIDE, XBl + 192*SM_STRIDE, wm0, wn0);
        else        mma_stageG<4,2,40,SM_STRIDE>(acc, Ah, Al, XBh + c*32*SM_STRIDE, XBl + c*32*SM_STRIDE, wm0, wn0);
    }

    __syncthreads();
    loadA(0, 0);

    #pragma unroll
    for (int mt = 0; mt < 4; mt++)
        #pragma unroll
        for (int nt = 0; nt < 4; nt++) {
            int col = wn0 + nt*8 + tig*2;
            #pragma unroll
            for (int rh = 0; rh < 2; rh++) {
                int row = wm0 + mt*16 + g + rh*8;
                float v0 = acc[mt][nt][rh*2+0], v1 = acc[mt][nt][rh*2+1];
                bf16 h0 = __float2bfloat16(v0), h1 = __float2bfloat16(v1);
                bf16 l0 = __float2bfloat16(v0 - __bfloat162float(h0));
                bf16 l1 = __float2bfloat16(v1 - __bfloat162float(h1));
                bf162 ph; ph.x = h0; ph.y = h1;
                bf162 pl; pl.x = l0; pl.y = l1;
                *(bf162*)(Y1h + row*SM_STRIDE + col) = ph;
                *(bf162*)(Y1l + row*SM_STRIDE + col) = pl;
                if (row < Nn) {
                    size_t di = ((size_t)b*NP + row)*NCH + n0 + col;
                    *(unsigned*)(gY1_h + di) = *reinterpret_cast<unsigned*>(&ph);
                    *(unsigned*)(gY1_l + di) = *reinterpret_cast<unsigned*>(&pl);
                }
            }
        }
    __syncthreads();

    #pragma unroll
    for (int i = 0; i < 4; i++) for (int j = 0; j < 4; j++) for (int r = 0; r < 4; r++) acc[i][j][r] = 0.f;

    #pragma unroll
    for (int c = 0; c < 7; c++) {
        cpa_wait<0>();
        __syncthreads();
        if (c < 6) loadA(c+1, (c+1)&1);
        const bf16* Ah = (const bf16*)(smem + LA(c&1,0));
        const bf16* Al = (const bf16*)(smem + LA(c&1,1));
        if (c == 6) mma_k8stage<4,40,SM_STRIDE>(acc, Ah, Al, Y1h + 192*SM_STRIDE, Y1l + 192*SM_STRIDE, wm0, wn0);
        else        mma_stageG<4,2,40,SM_STRIDE>(acc, Ah, Al, Y1h + c*32*SM_STRIDE, Y1l + c*32*SM_STRIDE, wm0, wn0);
    }

    #pragma unroll
    for (int mt = 0; mt < 4; mt++)
        #pragma unroll
        for (int nt = 0; nt < 4; nt++) {
            int col = wn0 + nt*8 + tig*2;
            #pragma unroll
            for (int rh = 0; rh < 2; rh++) {
                int row = wm0 + mt*16 + g + rh*8;
                if (row < Nn) {
                    int xo = row*SM_STRIDE + col;
                    float x0 = __bfloat162float(XBh[xo])   + __bfloat162float(XBl[xo]);
                    float x1 = __bfloat162float(XBh[xo+1]) + __bfloat162float(XBl[xo+1]);
                    float v0 = 2.f*acc[mt][nt][rh*2+0] - x0;
                    float v1 = 2.f*acc[mt][nt][rh*2+1] - x1;
                    bf16 h0 = __float2bfloat16(v0), h1 = __float2bfloat16(v1);
                    bf16 l0 = __float2bfloat16(v0 - __bfloat162float(h0));
                    bf16 l1 = __float2bfloat16(v1 - __bfloat162float(h1));
                    bf162 ph; ph.x = h0; ph.y = h1;
                    bf162 pl; pl.x = l0; pl.y = l1;
                    size_t di = ((size_t)b*NP + row)*NCH + n0 + col;
                    *(unsigned*)(gY2_h + di) = *reinterpret_cast<unsigned*>(&ph);
                    *(unsigned*)(gY2_l + di) = *reinterpret_cast<unsigned*>(&pl);
                }
            }
        }
}

// ---------------- fused mix+right, 256 threads ------------------------------
#define GSTR     200
#define OFF_GH   0
#define OFF_GL   80000
#define OFF_POOL 160000
#define P1_S(hl)     (OFF_POOL + (hl)*13312)                 // 64 x 104 bf16
#define P1_W(buf,hl) (OFF_POOL + 26624 + (buf)*13824 + (hl)*6912)  // 48 x 72 bf16
#define FUSED_SMEM   228096

__global__ __launch_bounds__(256) void k_fused(const float* __restrict__ bias,
                                               float* __restrict__ out) {
    extern __shared__ __align__(128) char smem[];
    unsigned sb = sptr(smem);
    int bi = blockIdx.x;
    int bb = bi / Nn, ii = bi % Nn;
    size_t abase = ((size_t)(bb*NP + ii))*NCH;
    int tid = threadIdx.x;
    int lane = tid & 31, warp = tid >> 5;
    int g = lane >> 2, tig = lane & 3;

    bf16* Ghp = (bf16*)(smem + OFF_GH);
    bf16* Glp = (bf16*)(smem + OFF_GL);

    auto loadW = [&](int st, int buf) {
        int nt3 = st >> 1, half = st & 1;
        #pragma unroll
        for (int i = 0; i < 3; i++) {
            int u = tid + i*256;
            int hl = u / 384, rem = u % 384;
            int r = rem >> 3, s = rem & 7;
            const bf16* wsrc = (hl ? gW_l : gW_h) + (size_t)(half*48 + r)*GW + nt3*64 + s*8;
            CPA(sb + P1_W(buf,hl) + r*144 + s*16, wsrc, 16);
        }
        CPA_COMMIT();
    };

    int p1m0 = (warp >> 1)*16, p1n0 = (warp & 1)*32;

    // ---- phase 1: build G in smem ----
    for (int qp = 0; qp < 4; qp++) {
        int q0 = qp*64;
        __syncthreads();
        #pragma unroll
        for (int i = 0; i < 3; i++) {
            int u = tid + i*256;
            int r = u / 12, s = u % 12;
            int q = q0 + r;
            int seg = s >> 2, cc = (s & 3)*8;
            int sz = (q < Nn) ? 16 : 0;
            int qq = (q < Nn) ? q : 0;
            size_t off = abase + (size_t)qq*32 + cc;
            const bf16 *ph, *pl;
            if (seg == 0)      { ph = gX_h  + off; pl = gX_l  + off; }
            else if (seg == 1) { ph = gY1_h + off; pl = gY1_l + off; }
            else               { ph = gY2_h + off; pl = gY2_l + off; }
            unsigned d = r*208 + s*16;
            CPA(sb + P1_S(0) + d, ph, sz);
            CPA(sb + P1_S(1) + d, pl, sz);
        }
        loadW(0, 0);
        loadW(1, 1);

        const bf16* Sh = (const bf16*)(smem + P1_S(0));
        const bf16* Sl = (const bf16*)(smem + P1_S(1));

        float acc1[1][4][4];
        #pragma unroll
        for (int st = 0; st < 6; st++) {
            if (st < 5) cpa_wait<1>(); else cpa_wait<0>();
            __syncthreads();
            if (st < 4) loadW(st+2, (st+2)%3);
            int nt3 = st >> 1, half = st & 1;
            const bf16* Wh = (const bf16*)(smem + P1_W(st%3,0));
            const bf16* Wl = (const bf16*)(smem + P1_W(st%3,1));
            if (half == 0) {
                #pragma unroll
                for (int j = 0; j < 4; j++) for (int r = 0; r < 4; r++) acc1[0][j][r] = 0.f;
            }
            mma_stageG<1,3,104,SM_STRIDE>(acc1, Sh + half*48, Sl + half*48, Wh, Wl, p1m0, p1n0);
            if (half == 1) {
                #pragma unroll
                for (int nt = 0; nt < 4; nt++) {
                    int col = nt3*64 + p1n0 + nt*8 + tig*2;
                    #pragma unroll
                    for (int rh = 0; rh < 2; rh++) {
                        int row = q0 + p1m0 + g + rh*8;
                        if (row < Nn) {
                            float v0 = acc1[0][nt][rh*2+0], v1 = acc1[0][nt][rh*2+1];
                            bf16 h0 = __float2bfloat16(v0), h1 = __float2bfloat16(v1);
                            bf16 l0 = __float2bfloat16(v0 - __bfloat162float(h0));
                            bf16 l1 = __float2bfloat16(v1 - __bfloat162float(h1));
                            bf162 ph; ph.x = h0; ph.y = h1;
                            bf162 pl; pl.x = l0; pl.y = l1;
                            *(bf162*)(Ghp + row*GSTR + col) = ph;
                            *(bf162*)(Glp + row*GSTR + col) = pl;
                        }
                    }
                }
            }
        }
    }

    __syncthreads();   // G complete; no block barriers below

    // ---- phase 2: warp-private A pipeline, 128-row j-tiles ----
    unsigned PA = sb + OFF_POOL + warp*6912;

    for (int jt = 0; jt < 2; jt++) {
        int jr = jt*128 + warp*16;
        float acc[8][4];
        #pragma unroll
        for (int j = 0; j < 8; j++) for (int r = 0; r < 4; r++) acc[j][r] = 0.f;

        auto issueA = [&](int c, int isL) {
            int phse = c >> 2, kc = c & 3;
            const bf16* src = isL ? (phse ? gR2_l : gRt_l) : (phse ? gR2_h : gRt_h);
            unsigned dst = PA + (isL ? 4608 : (c & 1)*2304);
            if (kc < 3) {
                int kq = kc*64;
                #pragma unroll
                for (int i = 0; i < 4; i++) {
                    int idx = lane + i*32, r = idx >> 3, s = idx & 7;
                    CPA(dst + r*144 + s*16, src + (size_t)(jr + r)*NP + kq + s*8, 16);
                }
            } else {
                if (lane < 16) CPA(dst + lane*144, src + (size_t)(jr + lane)*NP + 192, 16);
            }
            CPA_COMMIT();
        };

        issueA(0, 0); issueA(0, 1); issueA(1, 0);

        #pragma unroll
        for (int c = 0; c < 8; c++) {
            int phse = c >> 2, kc = c & 3;
            int coff = phse ? 128 : 64;
            const bf16* Ah = (const bf16*)(smem + OFF_POOL + warp*6912 + (c & 1)*2304);
            const bf16* Al = (const bf16*)(smem + OFF_POOL + warp*6912 + 4608);

            if (c == 7) cpa_wait<1>(); else cpa_wait<2>();
            __syncwarp();
            if (kc < 3) {
                #pragma unroll
                for (int ks = 0; ks < 4; ks++) {
                    unsigned a4[4];
                    LDA4(a4, sptr(Ah + (lane & 15)*72 + ks*16 + (lane >> 4)*8));
                    int rr = kc*64 + ks*16 + (lane & 15);
                    #pragma unroll
                    for (int nt = 0; nt < 8; nt++) {
                        unsigned bh[2], bl[2];
                        LDB2(bh, sptr(Ghp + rr*GSTR + coff + nt*8));
                        LDB2(bl, sptr(Glp + rr*GSTR + coff + nt*8));
                        mma_bf16(acc[nt], a4, bh);
                        mma_bf16(acc[nt], a4, bl);
                    }
                }
            } else {
                unsigned a2[2];
                LDA2(a2, sptr(Ah + (lane & 15)*72));
                int rr = 192 + (lane & 7);
                #pragma unroll
                for (int nt = 0; nt < 8; nt++) {
                    unsigned bh, bl;
                    LDB1(bh, sptr(Ghp + rr*GSTR + coff + nt*8));
                    LDB1(bl, sptr(Glp + rr*GSTR + coff + nt*8));
                    mma_bf16_k8(acc[nt], a2, bh);
                    mma_bf16_k8(acc[nt], a2, bl);
                }
            }

            if (c == 7) cpa_wait<0>(); else cpa_wait<1>();
            __syncwarp();
            if (kc < 3) {
                #pragma unroll
                for (int ks = 0; ks < 4; ks++) {
                    unsigned a4[4];
                    LDA4(a4, sptr(Al + (lane & 15)*72 + ks*16 + (lane >> 4)*8));
                    int rr = kc*64 + ks*16 + (lane & 15);
                    #pragma unroll
                    for (int nt = 0; nt < 8; nt++) {
                        unsigned bh[2];
                        LDB2(bh, sptr(Ghp + rr*GSTR + coff + nt*8));
                        mma_bf16(acc[nt], a4, bh);
                    }
                }
            } else {
                unsigned a2[2];
                LDA2(a2, sptr(Al + (lane & 15)*72));
                int rr = 192 + (lane & 7);
                #pragma unroll
                for (int nt = 0; nt < 8; nt++) {
                    unsigned bh;
                    LDB1(bh, sptr(Ghp + rr*GSTR + coff + nt*8));
                    mma_bf16_k8(acc[nt], a2, bh);
                }
            }
            if (c < 7) { issueA(c+1, 1); if (c < 6) issueA(c+2, 0); }
        }

        #pragma unroll
        for (int nt = 0; nt < 8; nt++) {
            int o = nt*8 + tig*2;
            #pragma unroll
            for (int rh = 0; rh < 2; rh++) {
                int j = jr + g + rh*8;
                if (j < Nn) {
                    float v0 = acc[nt][rh*2+0], v1 = acc[nt][rh*2+1];
                    int gr = j*GSTR;
                    float g0a = __bfloat162float(Ghp[gr + o])       + __bfloat162float(Glp[gr + o]);
                    float g0b = __bfloat162float(Ghp[gr + o + 1])   + __bfloat162float(Glp[gr + o + 1]);
                    float g2a = __bfloat162float(Ghp[gr + 128 + o]) + __bfloat162float(Glp[gr + 128 + o]);
                    float g2b = __bfloat162float(Ghp[gr + 128 + o + 1]) + __bfloat162float(Glp[gr + 128 + o + 1]);
                    size_t oi = ((size_t)bi*Nn + j)*64 + o;
                    out[oi]     = bias[o]     + g0a - g2a + v0;
                    out[oi + 1] = bias[o + 1] + g0b - g2b + v1;
                }
            }
        }
    }
}

// ---------------------------------------------------------------------------
extern "C" void kernel_launch(void* const* d_in, const int* in_sizes, int n_in,
                              void* d_out, int out_size) {
    const float* x    = (const float*)d_in[0];
    const float* adj  = (const float*)d_in[1];
    const float* w    = (const float*)d_in[2];
    const float* bias = (const float*)d_in[3];
    float* out = (float*)d_out;

    cudaFuncSetAttribute(k_leftfused, cudaFuncAttributeMaxDynamicSharedMemorySize, LEFT_SMEM);
    cudaFuncSetAttribute(k_fused,     cudaFuncAttributeMaxDynamicSharedMemorySize, FUSED_SMEM);

    k_deg<<<Nn, 256>>>(adj);                     // parallel degree sums
    k_buildA<<<(NP*NP + 255)/256, 256>>>(adj);
    k_R2<<<dim3(16, 16), dim3(16, 16)>>>();
    k_prepsplit<<<768 + 12800 + 96, 256>>>(x, w);

    k_leftfused<<<dim3(100, Bx), 256, LEFT_SMEM>>>();
    k_fused<<<1600, 256, FUSED_SMEM>>>(bias, out);
}

// round 16
// speedup vs baseline: 1.5362x; 1.0029x over previous
#include <cuda_runtime.h>
#include <cuda_bf16.h>
#include <cstdint>

#define Nn   200
#define NP   256
#define Bx   8
#define NCH  6400
#define GW   192

typedef __nv_bfloat16 bf16;
typedef __nv_bfloat162 bf162;

// ---------------- static scratch ----------------
__device__ float g_d0[NP];
__device__ float g_d1[NP];
__device__ float g_Afp[NP*NP];
__device__ float g_Rtf[NP*NP];
__device__ float g_R2f[NP*NP];
__device__ bf16  gA_h[NP*NP],  gA_l[NP*NP];
__device__ bf16  gRt_h[NP*NP], gRt_l[NP*NP];
__device__ bf16  gR2_h[NP*NP], gR2_l[NP*NP];
__device__ bf16  gX_h[(size_t)Bx*NP*NCH],  gX_l[(size_t)Bx*NP*NCH];
__device__ bf16  gY1_h[(size_t)Bx*NP*NCH], gY1_l[(size_t)Bx*NP*NCH];
__device__ bf16  gY2_h[(size_t)Bx*NP*NCH], gY2_l[(size_t)Bx*NP*NCH];
__device__ bf16  gW_h[128*GW], gW_l[128*GW];            // [k=128][n=192]

// ---------------- prep kernels ----------------
__global__ void k_deg(const float* __restrict__ adj) {
    int i = blockIdx.x;
    int tid = threadIdx.x;
    float cs = 0.f, rs = 0.f;
    if (tid < Nn && tid != i) {
        cs = adj[tid*Nn + i];
        rs = adj[i*Nn + tid];
    }
    __shared__ float scs[256], srs[256];
    scs[tid] = cs; srs[tid] = rs;
    __syncthreads();
    #pragma unroll
    for (int s = 128; s > 0; s >>= 1) {
        if (tid < s) { scs[tid] += scs[tid+s]; srs[tid] += srs[tid+s]; }
        __syncthreads();
    }
    if (tid == 0) {
        g_d0[i] = (scs[0] > 0.f) ? rsqrtf(scs[0]) : 0.f;
        g_d1[i] = (srs[0] > 0.f) ? rsqrtf(srs[0]) : 0.f;
    }
}
__global__ void k_buildA(const float* __restrict__ adj) {
    int idx = blockIdx.x * blockDim.x + threadIdx.x;
    if (idx < NP*NP) {
        int e = idx / NP, b = idx % NP;
        float v = 0.f;
        if (e < Nn && b < Nn && e != b) v = g_d0[b] * adj[b*Nn + e] * g_d1[e];
        g_Afp[e*NP + b] = v;
        g_Rtf[b*NP + e] = v;
    }
}
__global__ void k_R2() {
    __shared__ float a[16][17], b[16][17];
    int tx = threadIdx.x, ty = threadIdx.y;
    int j = blockIdx.y*16 + ty, q = blockIdx.x*16 + tx;
    float s = 0.f;
    for (int p0 = 0; p0 < NP; p0 += 16) {
        a[ty][tx] = g_Rtf[j*NP + p0 + tx];
        b[ty][tx] = g_Rtf[(p0+ty)*NP + q];
        __syncthreads();
        #pragma unroll
        for (int p = 0; p < 16; p++) s += a[ty][p]*b[p][tx];
        __syncthreads();
    }
    g_R2f[j*NP + q] = 2.f*s;
}
static __device__ __forceinline__ unsigned pack2(float a, float b) {
    bf162 t; t.x = __float2bfloat16(a); t.y = __float2bfloat16(b);
    return *reinterpret_cast<unsigned*>(&t);
}
__global__ void k_prepsplit(const float* __restrict__ x, const float* __restrict__ w) {
    int b = blockIdx.x;
    int tid = threadIdx.x;
    if (b < 768) {
        int which = b / 256;
        const float* s; bf16 *h, *l;
        if (which == 0)      { s = g_Afp; h = gA_h;  l = gA_l;  }
        else if (which == 1) { s = g_Rtf; h = gRt_h; l = gRt_l; }
        else                 { s = g_R2f; h = gR2_h; l = gR2_l; }
        int i = (b % 256)*256 + tid;
        float v = s[i];
        bf16 hh = __float2bfloat16(v);
        h[i] = hh;
        l[i] = __float2bfloat16(v - __bfloat162float(hh));
    } else if (b < 768 + 12800) {
        size_t i4 = ((size_t)(b - 768)*256 + tid) * 4;
        int col = (int)(i4 % NCH);
        int r   = (int)((i4 / NCH) % NP);
        int bb  = (int)(i4 / ((size_t)NP*NCH));
        float v0 = 0.f, v1 = 0.f, v2 = 0.f, v3 = 0.f;
        if (r < Nn) {
            const float4 xv = *reinterpret_cast<const float4*>(x + ((size_t)bb*Nn + r)*NCH + col);
            v0 = xv.x; v1 = xv.y; v2 = xv.z; v3 = xv.w;
        }
        bf16 h0 = __float2bfloat16(v0), h1 = __float2bfloat16(v1);
        bf16 h2 = __float2bfloat16(v2), h3 = __float2bfloat16(v3);
        float l0 = v0 - __bfloat162float(h0), l1 = v1 - __bfloat162float(h1);
        float l2 = v2 - __bfloat162float(h2), l3 = v3 - __bfloat162float(h3);
        bf162 ph0; ph0.x = h0; ph0.y = h1;
        bf162 ph1; ph1.x = h2; ph1.y = h3;
        uint2 hv = make_uint2(*reinterpret_cast<unsigned*>(&ph0), *reinterpret_cast<unsigned*>(&ph1));
        uint2 lv = make_uint2(pack2(l0, l1), pack2(l2, l3));
        *reinterpret_cast<uint2*>(gX_h + i4) = hv;
        *reinterpret_cast<uint2*>(gX_l + i4) = lv;
    } else {
        int i = (b - 768 - 12800)*256 + tid;
        int k = i / GW, n = i % GW;
        float v = 0.f;
        if (k < 96) {
            int k1 = k / 32, c = k & 31;
            int k2 = n / 64, o = n & 63;
            v = w[o*288 + (k1*3 + k2)*32 + c];
        }
        bf16 hh = __float2bfloat16(v);
        gW_h[i] = hh;
        gW_l[i] = __float2bfloat16(v - __bfloat162float(hh));
    }
}

// ---------------- mma/async helpers ----------------
static __device__ __forceinline__ unsigned sptr(const void* p) {
    return (unsigned)__cvta_generic_to_shared(p);
}
static __device__ __forceinline__ void mma_bf16(float* c, const unsigned* a, const unsigned* b) {
    asm volatile("mma.sync.aligned.m16n8k16.row.col.f32.bf16.bf16.f32 "
        "{%0,%1,%2,%3},{%4,%5,%6,%7},{%8,%9},{%0,%1,%2,%3};\n"
        : "+f"(c[0]), "+f"(c[1]), "+f"(c[2]), "+f"(c[3])
        : "r"(a[0]), "r"(a[1]), "r"(a[2]), "r"(a[3]), "r"(b[0]), "r"(b[1]));
}
static __device__ __forceinline__ void mma_bf16_k8(float* c, const unsigned* a, unsigned b) {
    asm volatile("mma.sync.aligned.m16n8k8.row.col.f32.bf16.bf16.f32 "
        "{%0,%1,%2,%3},{%4,%5},{%6},{%0,%1,%2,%3};\n"
        : "+f"(c[0]), "+f"(c[1]), "+f"(c[2]), "+f"(c[3])
        : "r"(a[0]), "r"(a[1]), "r"(b));
}
#define LDB2(bq, addr) asm volatile( \
    "ldmatrix.sync.aligned.m8n8.x2.trans.shared.b16 {%0,%1},[%2];" \
    : "=r"((bq)[0]), "=r"((bq)[1]) : "r"(addr))
#define LDB1(b, addr) asm volatile( \
    "ldmatrix.sync.aligned.m8n8.x1.trans.shared.b16 {%0},[%1];" \
    : "=r"(b) : "r"(addr))
#define LDA4(aq, addr) asm volatile( \
    "ldmatrix.sync.aligned.m8n8.x4.shared.b16 {%0,%1,%2,%3},[%4];" \
    : "=r"((aq)[0]), "=r"((aq)[1]), "=r"((aq)[2]), "=r"((aq)[3]) : "r"(addr))
#define LDA2(aq, addr) asm volatile( \
    "ldmatrix.sync.aligned.m8n8.x2.shared.b16 {%0,%1},[%2];" \
    : "=r"((aq)[0]), "=r"((aq)[1]) : "r"(addr))

#define SM_STRIDE 72

#define CPA(dst, src, sz) asm volatile( \
    "cp.async.cg.shared.global [%0], [%1], 16, %2;" :: "r"(dst), "l"(src), "r"(sz))
#define CPA_COMMIT() asm volatile("cp.async.commit_group;")
template<int N>
static __device__ __forceinline__ void cpa_wait() {
    asm volatile("cp.async.wait_group %0;" :: "n"(N));
}

// MTx16(M) x 64(N) x KSN*16(K), 3-pass split; A via ldmatrix.x4
template<int MT, int KSN, int AS, int BS>
static __device__ __forceinline__ void mma_stageG(float (*acc)[4][4],
        const bf16* Ah, const bf16* Al, const bf16* Bh, const bf16* Bl,
        int wm0, int wn0) {
    int lane = threadIdx.x & 31;
    int arow = lane & 15;
    int acol = (lane >> 4) * 8;
    #pragma unroll
    for (int kk = 0; kk < KSN; kk++) {
        int kb = kk*16;
        unsigned aH[MT][4], aL[MT][4], bH[4][2], bL[4][2];
        #pragma unroll
        for (int mt = 0; mt < MT; mt++) {
            int r = wm0 + mt*16 + arow;
            LDA4(aH[mt], sptr(Ah + r*AS + kb + acol));
            LDA4(aL[mt], sptr(Al + r*AS + kb + acol));
        }
        int rr = kb + (lane & 15);
        #pragma unroll
        for (int nt = 0; nt < 4; nt++) {
            LDB2(bH[nt], sptr(Bh + rr*BS + wn0 + nt*8));
            LDB2(bL[nt], sptr(Bl + rr*BS + wn0 + nt*8));
        }
        #pragma unroll
        for (int mt = 0; mt < MT; mt++)
            #pragma unroll
            for (int nt = 0; nt < 4; nt++) {
                mma_bf16(acc[mt][nt], aH[mt], bH[nt]);
                mma_bf16(acc[mt][nt], aH[mt], bL[nt]);
                mma_bf16(acc[mt][nt], aL[mt], bH[nt]);
            }
    }
}

// single k8 step (3-pass)
template<int MT, int AS, int BS>
static __device__ __forceinline__ void mma_k8stage(float (*acc)[4][4],
        const bf16* Ah, const bf16* Al, const bf16* Bh, const bf16* Bl,
        int wm0, int wn0) {
    int lane = threadIdx.x & 31;
    int arow = lane & 15;
    unsigned aH[MT][2], aL[MT][2], bH[4], bL[4];
    #pragma unroll
    for (int mt = 0; mt < MT; mt++) {
        int r = wm0 + mt*16 + arow;
        LDA2(aH[mt], sptr(Ah + r*AS));
        LDA2(aL[mt], sptr(Al + r*AS));
    }
    int rr = lane & 7;
    #pragma unroll
    for (int nt = 0; nt < 4; nt++) {
        LDB1(bH[nt], sptr(Bh + rr*BS + wn0 + nt*8));
        LDB1(bL[nt], sptr(Bl + rr*BS + wn0 + nt*8));
    }
    #pragma unroll
    for (int mt = 0; mt < MT; mt++)
        #pragma unroll
        for (int nt = 0; nt < 4; nt++) {
            mma_bf16_k8(acc[mt][nt], aH[mt], bH[nt]);
            mma_bf16_k8(acc[mt][nt], aH[mt], bL[nt]);
            mma_bf16_k8(acc[mt][nt], aL[mt], bH[nt]);
        }
}

// ---------------- fused left: Y1 = A@X, Y2 = 2*A@Y1 - X (one kernel) --------
#define XB_H   0
#define XB_L   36864
#define Y1S_H  73728
#define Y1S_L  110592
#define LA(st,hl) (147456 + (st)*40960 + (hl)*20480)   // 256 x 32 bf16, stride 40
#define LEFT_SMEM 229376

__global__ __launch_bounds__(256) void k_leftfused() {
    extern __shared__ __align__(128) char smem[];
    unsigned sb = sptr(smem);
    int n0 = blockIdx.x*64, b = blockIdx.y;
    int tid = threadIdx.x;
    int lane = tid & 31, warp = tid >> 5;
    int g = lane >> 2, tig = lane & 3;
    int wm0 = (warp >> 1)*64, wn0 = (warp & 1)*32;

    const bf16* XBh = (const bf16*)(smem + XB_H);
    const bf16* XBl = (const bf16*)(smem + XB_L);
    bf16* Y1h = (bf16*)(smem + Y1S_H);
    bf16* Y1l = (bf16*)(smem + Y1S_L);

    auto loadA = [&](int c, int st) {
        int k0 = c*32;
        #pragma unroll
        for (int i = 0; i < 8; i++) {
            int u = tid + i*256;
            int hl = u >> 10, rem = u & 1023;
            int r = rem >> 2, s = rem & 3;
            const bf16* src = (hl ? gA_l : gA_h) + (size_t)r*NP + k0 + s*8;
            CPA(sb + LA(st,hl) + r*80 + s*16, src, 16);
        }
        CPA_COMMIT();
    };

    #pragma unroll
    for (int i = 0; i < 16; i++) {
        int u = tid + i*256;
        int hl = u >> 11, rem = u & 2047;
        int r = rem >> 3, s = rem & 7;
        const bf16* src = (hl ? gX_l : gX_h) + ((size_t)b*NP + r)*NCH + n0 + s*8;
        CPA(sb + (hl ? XB_L : XB_H) + r*144 + s*16, src, 16);
    }
    loadA(0, 0);

    float acc[4][4][4];
    #pragma unroll
    for (int i = 0; i < 4; i++) for (int j = 0; j < 4; j++) for (int r = 0; r < 4; r++) acc[i][j][r] = 0.f;

    #pragma unroll
    for (int c = 0; c < 7; c++) {
        cpa_wait<0>();
        __syncthreads();
        if (c < 6) loadA(c+1, (c+1)&1);
        const bf16* Ah = (const bf16*)(smem + LA(c&1,0));
        const bf16* Al = (const bf16*)(smem + LA(c&1,1));
        if (c == 6) mma_k8stage<4,40,SM_STRIDE>(acc, Ah, Al, XBh + 192*SM_STRIDE, XBl + 192*SM_STRIDE, wm0, wn0);
        else        mma_stageG<4,2,40,SM_STRIDE>(acc, Ah, Al, XBh + c*32*SM_STRIDE, XBl + c*32*SM_STRIDE, wm0, wn0);
    }

    __syncthreads();
    loadA(0, 0);

    #pragma unroll
    for (int mt = 0; mt < 4; mt++)
        #pragma unroll
        for (int nt = 0; nt < 4; nt++) {
            int col = wn0 + nt*8 + tig*2;
            #pragma unroll
            for (int rh = 0; rh < 2; rh++) {
                int row = wm0 + mt*16 + g + rh*8;
                float v0 = acc[mt][nt][rh*2+0], v1 = acc[mt][nt][rh*2+1];
                bf16 h0 = __float2bfloat16(v0), h1 = __float2bfloat16(v1);
                bf16 l0 = __float2bfloat16(v0 - __bfloat162float(h0));
                bf16 l1 = __float2bfloat16(v1 - __bfloat162float(h1));
                bf162 ph; ph.x = h0; ph.y = h1;
                bf162 pl; pl.x = l0; pl.y = l1;
                *(bf162*)(Y1h + row*SM_STRIDE + col) = ph;
                *(bf162*)(Y1l + row*SM_STRIDE + col) = pl;
                if (row < Nn) {
                    size_t di = ((size_t)b*NP + row)*NCH + n0 + col;
                    *(unsigned*)(gY1_h + di) = *reinterpret_cast<unsigned*>(&ph);
                    *(unsigned*)(gY1_l + di) = *reinterpret_cast<unsigned*>(&pl);
                }
            }
        }
    __syncthreads();

    #pragma unroll
    for (int i = 0; i < 4; i++) for (int j = 0; j < 4; j++) for (int r = 0; r < 4; r++) acc[i][j][r] = 0.f;

    #pragma unroll
    for (int c = 0; c < 7; c++) {
        cpa_wait<0>();
        __syncthreads();
        if (c < 6) loadA(c+1, (c+1)&1);
        const bf16* Ah = (const bf16*)(smem + LA(c&1,0));
        const bf16* Al = (const bf16*)(smem + LA(c&1,1));
        if (c == 6) mma_k8stage<4,40,SM_STRIDE>(acc, Ah, Al, Y1h + 192*SM_STRIDE, Y1l + 192*SM_STRIDE, wm0, wn0);
        else        mma_stageG<4,2,40,SM_STRIDE>(acc, Ah, Al, Y1h + c*32*SM_STRIDE, Y1l + c*32*SM_STRIDE, wm0, wn0);
    }

    #pragma unroll
    for (int mt = 0; mt < 4; mt++)
        #pragma unroll
        for (int nt = 0; nt < 4; nt++) {
            int col = wn0 + nt*8 + tig*2;
            #pragma unroll
            for (int rh = 0; rh < 2; rh++) {
                int row = wm0 + mt*16 + g + rh*8;
                if (row < Nn) {
                    int xo = row*SM_STRIDE + col;
                    float x0 = __bfloat162float(XBh[xo])   + __bfloat162float(XBl[xo]);
                    float x1 = __bfloat162float(XBh[xo+1]) + __bfloat162float(XBl[xo+1]);
                    float v0 = 2.f*acc[mt][nt][rh*2+0] - x0;
                    float v1 = 2.f*acc[mt][nt][rh*2+1] - x1;
                    bf16 h0 = __float2bfloat16(v0), h1 = __float2bfloat16(v1);
                    bf16 l0 = __float2bfloat16(v0 - __bfloat162float(h0));
                    bf16 l1 = __float2bfloat16(v1 - __bfloat162float(h1));
                    bf162 ph; ph.x = h0; ph.y = h1;
                    bf162 pl; pl.x = l0; pl.y = l1;
                    size_t di = ((size_t)b*NP + row)*NCH + n0 + col;
                    *(unsigned*)(gY2_h + di) = *reinterpret_cast<unsigned*>(&ph);
                    *(unsigned*)(gY2_l + di) = *reinterpret_cast<unsigned*>(&pl);
                }
            }
        }
}

// ---------------- fused mix+right, 256 threads ------------------------------
#define GSTR     200
#define OFF_GH   0
#define OFF_GL   80000
#define OFF_POOL 160000
#define P1_S(hl)     (OFF_POOL + (hl)*13312)                 // 64 x 104 bf16
#define P1_W(buf,hl) (OFF_POOL + 26624 + (buf)*13824 + (hl)*6912)  // 48 x 72 bf16
#define FUSED_SMEM   228096

__global__ __launch_bounds__(256) void k_fused(const float* __restrict__ bias,
                                               float* __restrict__ out) {
    extern __shared__ __align__(128) char smem[];
    unsigned sb = sptr(smem);
    int bi = blockIdx.x;
    int bb = bi / Nn, ii = bi % Nn;
    size_t abase = ((size_t)(bb*NP + ii))*NCH;
    int tid = threadIdx.x;
    int lane = tid & 31, warp = tid >> 5;
    int g = lane >> 2, tig = lane & 3;

    bf16* Ghp = (bf16*)(smem + OFF_GH);
    bf16* Glp = (bf16*)(smem + OFF_GL);

    auto loadW = [&](int st, int buf) {
        int nt3 = st >> 1, half = st & 1;
        #pragma unroll
        for (int i = 0; i < 3; i++) {
            int u = tid + i*256;
            int hl = u / 384, rem = u % 384;
            int r = rem >> 3, s = rem & 7;
            const bf16* wsrc = (hl ? gW_l : gW_h) + (size_t)(half*48 + r)*GW + nt3*64 + s*8;
            CPA(sb + P1_W(buf,hl) + r*144 + s*16, wsrc, 16);
        }
        CPA_COMMIT();
    };

    int p1m0 = (warp >> 1)*16, p1n0 = (warp & 1)*32;

    // ---- phase 1: build G in smem ----
    for (int qp = 0; qp < 4; qp++) {
        int q0 = qp*64;
        __syncthreads();
        #pragma unroll
        for (int i = 0; i < 3; i++) {
            int u = tid + i*256;
            int r = u / 12, s = u % 12;
            int q = q0 + r;
            int seg = s >> 2, cc = (s & 3)*8;
            int sz = (q < Nn) ? 16 : 0;
            int qq = (q < Nn) ? q : 0;
            size_t off = abase + (size_t)qq*32 + cc;
            const bf16 *ph, *pl;
            if (seg == 0)      { ph = gX_h  + off; pl = gX_l  + off; }
            else if (seg == 1) { ph = gY1_h + off; pl = gY1_l + off; }
            else               { ph = gY2_h + off; pl = gY2_l + off; }
            unsigned d = r*208 + s*16;
            CPA(sb + P1_S(0) + d, ph, sz);
            CPA(sb + P1_S(1) + d, pl, sz);
        }
        loadW(0, 0);
        loadW(1, 1);

        const bf16* Sh = (const bf16*)(smem + P1_S(0));
        const bf16* Sl = (const bf16*)(smem + P1_S(1));

        float acc1[1][4][4];
        #pragma unroll
        for (int st = 0; st < 6; st++) {
            if (st < 5) cpa_wait<1>(); else cpa_wait<0>();
            __syncthreads();
            if (st < 4) loadW(st+2, (st+2)%3);
            int nt3 = st >> 1, half = st & 1;
            const bf16* Wh = (const bf16*)(smem + P1_W(st%3,0));
            const bf16* Wl = (const bf16*)(smem + P1_W(st%3,1));
            if (half == 0) {
                #pragma unroll
                for (int j = 0; j < 4; j++) for (int r = 0; r < 4; r++) acc1[0][j][r] = 0.f;
            }
            mma_stageG<1,3,104,SM_STRIDE>(acc1, Sh + half*48, Sl + half*48, Wh, Wl, p1m0, p1n0);
            if (half == 1) {
                #pragma unroll
                for (int nt = 0; nt < 4; nt++) {
                    int col = nt3*64 + p1n0 + nt*8 + tig*2;
                    #pragma unroll
                    for (int rh = 0; rh < 2; rh++) {
                        int row = q0 + p1m0 + g + rh*8;
                        if (row < Nn) {
                            float v0 = acc1[0][nt][rh*2+0], v1 = acc1[0][nt][rh*2+1];
                            bf16 h0 = __float2bfloat16(v0), h1 = __float2bfloat16(v1);
                            bf16 l0 = __float2bfloat16(v0 - __bfloat162float(h0));
                            bf16 l1 = __float2bfloat16(v1 - __bfloat162float(h1));
                            bf162 ph; ph.x = h0; ph.y = h1;
                            bf162 pl; pl.x = l0; pl.y = l1;
                            *(bf162*)(Ghp + row*GSTR + col) = ph;
                            *(bf162*)(Glp + row*GSTR + col) = pl;
                        }
                    }
                }
            }
        }
    }

    __syncthreads();   // G complete; no block barriers below

    // ---- phase 2: warp-private A, 3-slot ring, single-B-read ----
    unsigned PA = sb + OFF_POOL + warp*6912;   // 3 slots x 2304 B

    for (int jt = 0; jt < 2; jt++) {
        int jr = jt*128 + warp*16;
        float acc[8][4];
        #pragma unroll
        for (int j = 0; j < 8; j++) for (int r = 0; r < 4; r++) acc[j][r] = 0.f;

        // load stream: li even = Ah chunk li/2, li odd = Al chunk li/2; slot li%3
        auto issueLd = [&](int li) {
            int c = li >> 1, isL = li & 1;
            int phse = c >> 2, kc = c & 3;
            const bf16* src = isL ? (phse ? gR2_l : gRt_l) : (phse ? gR2_h : gRt_h);
            unsigned dst = PA + (li % 3)*2304;
            if (kc < 3) {
                int kq = kc*64;
                #pragma unroll
                for (int i = 0; i < 4; i++) {
                    int idx = lane + i*32, r = idx >> 3, s = idx & 7;
                    CPA(dst + r*144 + s*16, src + (size_t)(jr + r)*NP + kq + s*8, 16);
                }
            } else {
                if (lane < 16) CPA(dst + lane*144, src + (size_t)(jr + lane)*NP + 192, 16);
            }
            CPA_COMMIT();
        };

        issueLd(0); issueLd(1); issueLd(2);

        #pragma unroll
        for (int c = 0; c < 8; c++) {
            int phse = c >> 2, kc = c & 3;
            int coff = phse ? 128 : 64;
            const bf16* Ah = (const bf16*)(smem + OFF_POOL + warp*6912 + ((2*c) % 3)*2304);
            const bf16* Al = (const bf16*)(smem + OFF_POOL + warp*6912 + ((2*c + 1) % 3)*2304);

            if (c == 7) cpa_wait<0>(); else cpa_wait<1>();
            __syncwarp();

            if (kc < 3) {
                #pragma unroll
                for (int ks = 0; ks < 4; ks++) {
                    unsigned a4h[4], a4l[4];
                    LDA4(a4h, sptr(Ah + (lane & 15)*72 + ks*16 + (lane >> 4)*8));
                    LDA4(a4l, sptr(Al + (lane & 15)*72 + ks*16 + (lane >> 4)*8));
                    int rr = kc*64 + ks*16 + (lane & 15);
                    #pragma unroll
                    for (int nt = 0; nt < 8; nt++) {
                        unsigned bh[2], bl[2];
                        LDB2(bh, sptr(Ghp + rr*GSTR + coff + nt*8));
                        LDB2(bl, sptr(Glp + rr*GSTR + coff + nt*8));
                        mma_bf16(acc[nt], a4h, bh);
                        mma_bf16(acc[nt], a4h, bl);
                        mma_bf16(acc[nt], a4l, bh);
                    }
                }
            } else {
                unsigned a2h[2], a2l[2];
                LDA2(a2h, sptr(Ah + (lane & 15)*72));
                LDA2(a2l, sptr(Al + (lane & 15)*72));
                int rr = 192 + (lane & 7);
                #pragma unroll
                for (int nt = 0; nt < 8; nt++) {
                    unsigned bh, bl;
                    LDB1(bh, sptr(Ghp + rr*GSTR + coff + nt*8));
                    LDB1(bl, sptr(Glp + rr*GSTR + coff + nt*8));
                    mma_bf16_k8(acc[nt], a2h, bh);
                    mma_bf16_k8(acc[nt], a2h, bl);
                    mma_bf16_k8(acc[nt], a2l, bh);
                }
            }

            if (c < 7) { issueLd(2*c + 3); if (c < 6) issueLd(2*c + 4); }
        }

        // epilogue: warp rows jr..jr+15
        #pragma unroll
        for (int nt = 0; nt < 8; nt++) {
            int o = nt*8 + tig*2;
            #pragma unroll
            for (int rh = 0; rh < 2; rh++) {
                int j = jr + g + rh*8;
                if (j < Nn) {
                    float v0 = acc[nt][rh*2+0], v1 = acc[nt][rh*2+1];
                    int gr = j*GSTR;
                    float g0a = __bfloat162float(Ghp[gr + o])       + __bfloat162float(Glp[gr + o]);
                    float g0b = __bfloat162float(Ghp[gr + o + 1])   + __bfloat162float(Glp[gr + o + 1]);
                    float g2a = __bfloat162float(Ghp[gr + 128 + o]) + __bfloat162float(Glp[gr + 128 + o]);
                    float g2b = __bfloat162float(Ghp[gr + 128 + o + 1]) + __bfloat162float(Glp[gr + 128 + o + 1]);
                    size_t oi = ((size_t)bi*Nn + j)*64 + o;
                    out[oi]     = bias[o]     + g0a - g2a + v0;
                    out[oi + 1] = bias[o + 1] + g0b - g2b + v1;
                }
            }
        }
    }
}

// ---------------------------------------------------------------------------
extern "C" void kernel_launch(void* const* d_in, const int* in_sizes, int n_in,
                              void* d_out, int out_size) {
    const float* x    = (const float*)d_in[0];
    const float* adj  = (const float*)d_in[1];
    const float* w    = (const float*)d_in[2];
    const float* bias = (const float*)d_in[3];
    float* out = (float*)d_out;

    cudaFuncSetAttribute(k_leftfused, cudaFuncAttributeMaxDynamicSharedMemorySize, LEFT_SMEM);
    cudaFuncSetAttribute(k_fused,     cudaFuncAttributeMaxDynamicSharedMemorySize, FUSED_SMEM);

    k_deg<<<Nn, 256>>>(adj);
    k_buildA<<<(NP*NP + 255)/256, 256>>>(adj);
    k_R2<<<dim3(16, 16), dim3(16, 16)>>>();
    k_prepsplit<<<768 + 12800 + 96, 256>>>(x, w);

    k_leftfused<<<dim3(100, Bx), 256, LEFT_SMEM>>>();
    k_fused<<<1600, 256, FUSED_SMEM>>>(bias, out);
}

// round 17
// speedup vs baseline: 1.5472x; 1.0072x over previous
#include <cuda_runtime.h>
#include <cuda_bf16.h>
#include <cstdint>

#define Nn   200
#define NP   256
#define Bx   8
#define NCH  6400
#define GW   192

typedef __nv_bfloat16 bf16;
typedef __nv_bfloat162 bf162;

// ---------------- static scratch ----------------
__device__ float g_d0[NP];
__device__ float g_d1[NP];
__device__ float g_Afp[NP*NP];
__device__ float g_Rtf[NP*NP];
__device__ float g_R2f[NP*NP];
__device__ bf16  gA_h[NP*NP],  gA_l[NP*NP];
__device__ bf16  gRt_h[NP*NP], gRt_l[NP*NP];
__device__ bf16  gR2_h[NP*NP], gR2_l[NP*NP];
__device__ bf16  gX_h[(size_t)Bx*NP*NCH],  gX_l[(size_t)Bx*NP*NCH];
__device__ bf16  gY1_h[(size_t)Bx*NP*NCH], gY1_l[(size_t)Bx*NP*NCH];
__device__ bf16  gY2_h[(size_t)Bx*NP*NCH], gY2_l[(size_t)Bx*NP*NCH];
__device__ bf16  gW_h[128*GW], gW_l[128*GW];            // [k=128][n=192]

// ---------------- prep kernels ----------------
__global__ void k_deg(const float* __restrict__ adj) {
    int i = blockIdx.x;
    int tid = threadIdx.x;
    float cs = 0.f, rs = 0.f;
    if (tid < Nn && tid != i) {
        cs = adj[tid*Nn + i];
        rs = adj[i*Nn + tid];
    }
    __shared__ float scs[256], srs[256];
    scs[tid] = cs; srs[tid] = rs;
    __syncthreads();
    #pragma unroll
    for (int s = 128; s > 0; s >>= 1) {
        if (tid < s) { scs[tid] += scs[tid+s]; srs[tid] += srs[tid+s]; }
        __syncthreads();
    }
    if (tid == 0) {
        g_d0[i] = (scs[0] > 0.f) ? rsqrtf(scs[0]) : 0.f;
        g_d1[i] = (srs[0] > 0.f) ? rsqrtf(srs[0]) : 0.f;
    }
}
__global__ void k_buildA(const float* __restrict__ adj) {
    int idx = blockIdx.x * blockDim.x + threadIdx.x;
    if (idx < NP*NP) {
        int e = idx / NP, b = idx % NP;
        float v = 0.f;
        if (e < Nn && b < Nn && e != b) v = g_d0[b] * adj[b*Nn + e] * g_d1[e];
        g_Afp[e*NP + b] = v;
        g_Rtf[b*NP + e] = v;
    }
}
__global__ void k_R2() {
    __shared__ float a[16][17], b[16][17];
    int tx = threadIdx.x, ty = threadIdx.y;
    int j = blockIdx.y*16 + ty, q = blockIdx.x*16 + tx;
    float s = 0.f;
    for (int p0 = 0; p0 < NP; p0 += 16) {
        a[ty][tx] = g_Rtf[j*NP + p0 + tx];
        b[ty][tx] = g_Rtf[(p0+ty)*NP + q];
        __syncthreads();
        #pragma unroll
        for (int p = 0; p < 16; p++) s += a[ty][p]*b[p][tx];
        __syncthreads();
    }
    g_R2f[j*NP + q] = 2.f*s;
}
static __device__ __forceinline__ unsigned pack2(float a, float b) {
    bf162 t; t.x = __float2bfloat16(a); t.y = __float2bfloat16(b);
    return *reinterpret_cast<unsigned*>(&t);
}
__global__ void k_prepsplit(const float* __restrict__ x, const float* __restrict__ w) {
    int b = blockIdx.x;
    int tid = threadIdx.x;
    if (b < 768) {
        int which = b / 256;
        const float* s; bf16 *h, *l;
        if (which == 0)      { s = g_Afp; h = gA_h;  l = gA_l;  }
        else if (which == 1) { s = g_Rtf; h = gRt_h; l = gRt_l; }
        else                 { s = g_R2f; h = gR2_h; l = gR2_l; }
        int i = (b % 256)*256 + tid;
        float v = s[i];
        bf16 hh = __float2bfloat16(v);
        h[i] = hh;
        l[i] = __float2bfloat16(v - __bfloat162float(hh));
    } else if (b < 768 + 12800) {
        size_t i4 = ((size_t)(b - 768)*256 + tid) * 4;
        int col = (int)(i4 % NCH);
        int r   = (int)((i4 / NCH) % NP);
        int bb  = (int)(i4 / ((size_t)NP*NCH));
        float v0 = 0.f, v1 = 0.f, v2 = 0.f, v3 = 0.f;
        if (r < Nn) {
            const float4 xv = *reinterpret_cast<const float4*>(x + ((size_t)bb*Nn + r)*NCH + col);
            v0 = xv.x; v1 = xv.y; v2 = xv.z; v3 = xv.w;
        }
        bf16 h0 = __float2bfloat16(v0), h1 = __float2bfloat16(v1);
        bf16 h2 = __float2bfloat16(v2), h3 = __float2bfloat16(v3);
        float l0 = v0 - __bfloat162float(h0), l1 = v1 - __bfloat162float(h1);
        float l2 = v2 - __bfloat162float(h2), l3 = v3 - __bfloat162float(h3);
        bf162 ph0; ph0.x = h0; ph0.y = h1;
        bf162 ph1; ph1.x = h2; ph1.y = h3;
        uint2 hv = make_uint2(*reinterpret_cast<unsigned*>(&ph0), *reinterpret_cast<unsigned*>(&ph1));
        uint2 lv = make_uint2(pack2(l0, l1), pack2(l2, l3));
        *reinterpret_cast<uint2*>(gX_h + i4) = hv;
        *reinterpret_cast<uint2*>(gX_l + i4) = lv;
    } else {
        int i = (b - 768 - 12800)*256 + tid;
        int k = i / GW, n = i % GW;
        float v = 0.f;
        if (k < 96) {
            int k1 = k / 32, c = k & 31;
            int k2 = n / 64, o = n & 63;
            v = w[o*288 + (k1*3 + k2)*32 + c];
        }
        bf16 hh = __float2bfloat16(v);
        gW_h[i] = hh;
        gW_l[i] = __float2bfloat16(v - __bfloat162float(hh));
    }
}

// ---------------- mma/async helpers ----------------
static __device__ __forceinline__ unsigned sptr(const void* p) {
    return (unsigned)__cvta_generic_to_shared(p);
}
static __device__ __forceinline__ void mma_bf16(float* c, const unsigned* a, const unsigned* b) {
    asm volatile("mma.sync.aligned.m16n8k16.row.col.f32.bf16.bf16.f32 "
        "{%0,%1,%2,%3},{%4,%5,%6,%7},{%8,%9},{%0,%1,%2,%3};\n"
        : "+f"(c[0]), "+f"(c[1]), "+f"(c[2]), "+f"(c[3])
        : "r"(a[0]), "r"(a[1]), "r"(a[2]), "r"(a[3]), "r"(b[0]), "r"(b[1]));
}
static __device__ __forceinline__ void mma_bf16_k8(float* c, const unsigned* a, unsigned b) {
    asm volatile("mma.sync.aligned.m16n8k8.row.col.f32.bf16.bf16.f32 "
        "{%0,%1,%2,%3},{%4,%5},{%6},{%0,%1,%2,%3};\n"
        : "+f"(c[0]), "+f"(c[1]), "+f"(c[2]), "+f"(c[3])
        : "r"(a[0]), "r"(a[1]), "r"(b));
}
#define LDB2(bq, addr) asm volatile( \
    "ldmatrix.sync.aligned.m8n8.x2.trans.shared.b16 {%0,%1},[%2];" \
    : "=r"((bq)[0]), "=r"((bq)[1]) : "r"(addr))
#define LDB1(b, addr) asm volatile( \
    "ldmatrix.sync.aligned.m8n8.x1.trans.shared.b16 {%0},[%1];" \
    : "=r"(b) : "r"(addr))
#define LDA4(aq, addr) asm volatile( \
    "ldmatrix.sync.aligned.m8n8.x4.shared.b16 {%0,%1,%2,%3},[%4];" \
    : "=r"((aq)[0]), "=r"((aq)[1]), "=r"((aq)[2]), "=r"((aq)[3]) : "r"(addr))
#define LDA2(aq, addr) asm volatile( \
    "ldmatrix.sync.aligned.m8n8.x2.shared.b16 {%0,%1},[%2];" \
    : "=r"((aq)[0]), "=r"((aq)[1]) : "r"(addr))

#define SM_STRIDE 72

#define CPA(dst, src, sz) asm volatile( \
    "cp.async.cg.shared.global [%0], [%1], 16, %2;" :: "r"(dst), "l"(src), "r"(sz))
#define CPA_COMMIT() asm volatile("cp.async.commit_group;")
template<int N>
static __device__ __forceinline__ void cpa_wait() {
    asm volatile("cp.async.wait_group %0;" :: "n"(N));
}

// MTx16(M) x 64(N) x KSN*16(K), 3-pass split; A via ldmatrix.x4
template<int MT, int KSN, int AS, int BS>
static __device__ __forceinline__ void mma_stageG(float (*acc)[4][4],
        const bf16* Ah, const bf16* Al, const bf16* Bh, const bf16* Bl,
        int wm0, int wn0) {
    int lane = threadIdx.x & 31;
    int arow = lane & 15;
    int acol = (lane >> 4) * 8;
    #pragma unroll
    for (int kk = 0; kk < KSN; kk++) {
        int kb = kk*16;
        unsigned aH[MT][4], aL[MT][4], bH[4][2], bL[4][2];
        #pragma unroll
        for (int mt = 0; mt < MT; mt++) {
            int r = wm0 + mt*16 + arow;
            LDA4(aH[mt], sptr(Ah + r*AS + kb + acol));
            LDA4(aL[mt], sptr(Al + r*AS + kb + acol));
        }
        int rr = kb + (lane & 15);
        #pragma unroll
        for (int nt = 0; nt < 4; nt++) {
            LDB2(bH[nt], sptr(Bh + rr*BS + wn0 + nt*8));
            LDB2(bL[nt], sptr(Bl + rr*BS + wn0 + nt*8));
        }
        #pragma unroll
        for (int mt = 0; mt < MT; mt++)
            #pragma unroll
            for (int nt = 0; nt < 4; nt++) {
                mma_bf16(acc[mt][nt], aH[mt], bH[nt]);
                mma_bf16(acc[mt][nt], aH[mt], bL[nt]);
                mma_bf16(acc[mt][nt], aL[mt], bH[nt]);
            }
    }
}

// single k8 step (3-pass)
template<int MT, int AS, int BS>
static __device__ __forceinline__ void mma_k8stage(float (*acc)[4][4],
        const bf16* Ah, const bf16* Al, const bf16* Bh, const bf16* Bl,
        int wm0, int wn0) {
    int lane = threadIdx.x & 31;
    int arow = lane & 15;
    unsigned aH[MT][2], aL[MT][2], bH[4], bL[4];
    #pragma unroll
    for (int mt = 0; mt < MT; mt++) {
        int r = wm0 + mt*16 + arow;
        LDA2(aH[mt], sptr(Ah + r*AS));
        LDA2(aL[mt], sptr(Al + r*AS));
    }
    int rr = lane & 7;
    #pragma unroll
    for (int nt = 0; nt < 4; nt++) {
        LDB1(bH[nt], sptr(Bh + rr*BS + wn0 + nt*8));
        LDB1(bL[nt], sptr(Bl + rr*BS + wn0 + nt*8));
    }
    #pragma unroll
    for (int mt = 0; mt < MT; mt++)
        #pragma unroll
        for (int nt = 0; nt < 4; nt++) {
            mma_bf16_k8(acc[mt][nt], aH[mt], bH[nt]);
            mma_bf16_k8(acc[mt][nt], aH[mt], bL[nt]);
            mma_bf16_k8(acc[mt][nt], aL[mt], bH[nt]);
        }
}

// ---------------- fused left: Y1 = A@X, Y2 = 2*A@Y1 - X (one kernel) --------
#define XB_H   0
#define XB_L   36864
#define Y1S_H  73728
#define Y1S_L  110592
#define LA(st,hl) (147456 + (st)*40960 + (hl)*20480)   // 256 x 32 bf16, stride 40
#define LEFT_SMEM 229376

__global__ __launch_bounds__(256) void k_leftfused() {
    extern __shared__ __align__(128) char smem[];
    unsigned sb = sptr(smem);
    int n0 = blockIdx.x*64, b = blockIdx.y;
    int tid = threadIdx.x;
    int lane = tid & 31, warp = tid >> 5;
    int g = lane >> 2, tig = lane & 3;
    int wm0 = (warp >> 1)*64, wn0 = (warp & 1)*32;

    const bf16* XBh = (const bf16*)(smem + XB_H);
    const bf16* XBl = (const bf16*)(smem + XB_L);
    bf16* Y1h = (bf16*)(smem + Y1S_H);
    bf16* Y1l = (bf16*)(smem + Y1S_L);

    auto loadA = [&](int c, int st) {
        int k0 = c*32;
        #pragma unroll
        for (int i = 0; i < 8; i++) {
            int u = tid + i*256;
            int hl = u >> 10, rem = u & 1023;
            int r = rem >> 2, s = rem & 3;
            const bf16* src = (hl ? gA_l : gA_h) + (size_t)r*NP + k0 + s*8;
            CPA(sb + LA(st,hl) + r*80 + s*16, src, 16);
        }
        CPA_COMMIT();
    };

    #pragma unroll
    for (int i = 0; i < 16; i++) {
        int u = tid + i*256;
        int hl = u >> 11, rem = u & 2047;
        int r = rem >> 3, s = rem & 7;
        const bf16* src = (hl ? gX_l : gX_h) + ((size_t)b*NP + r)*NCH + n0 + s*8;
        CPA(sb + (hl ? XB_L : XB_H) + r*144 + s*16, src, 16);
    }
    loadA(0, 0);

    float acc[4][4][4];
    #pragma unroll
    for (int i = 0; i < 4; i++) for (int j = 0; j < 4; j++) for (int r = 0; r < 4; r++) acc[i][j][r] = 0.f;

    #pragma unroll
    for (int c = 0; c < 7; c++) {
        cpa_wait<0>();
        __syncthreads();
        if (c < 6) loadA(c+1, (c+1)&1);
        const bf16* Ah = (const bf16*)(smem + LA(c&1,0));
        const bf16* Al = (const bf16*)(smem + LA(c&1,1));
        if (c == 6) mma_k8stage<4,40,SM_STRIDE>(acc, Ah, Al, XBh + 192*SM_STRIDE, XBl + 192*SM_STRIDE, wm0, wn0);
        else        mma_stageG<4,2,40,SM_STRIDE>(acc, Ah, Al, XBh + c*32*SM_STRIDE, XBl + c*32*SM_STRIDE, wm0, wn0);
    }

    __syncthreads();
    loadA(0, 0);

    #pragma unroll
    for (int mt = 0; mt < 4; mt++)
        #pragma unroll
        for (int nt = 0; nt < 4; nt++) {
            int col = wn0 + nt*8 + tig*2;
            #pragma unroll
            for (int rh = 0; rh < 2; rh++) {
                int row = wm0 + mt*16 + g + rh*8;
                float v0 = acc[mt][nt][rh*2+0], v1 = acc[mt][nt][rh*2+1];
                bf16 h0 = __float2bfloat16(v0), h1 = __float2bfloat16(v1);
                bf16 l0 = __float2bfloat16(v0 - __bfloat162float(h0));
                bf16 l1 = __float2bfloat16(v1 - __bfloat162float(h1));
                bf162 ph; ph.x = h0; ph.y = h1;
                bf162 pl; pl.x = l0; pl.y = l1;
                *(bf162*)(Y1h + row*SM_STRIDE + col) = ph;
                *(bf162*)(Y1l + row*SM_STRIDE + col) = pl;
                if (row < Nn) {
                    size_t di = ((size_t)b*NP + row)*NCH + n0 + col;
                    *(unsigned*)(gY1_h + di) = *reinterpret_cast<unsigned*>(&ph);
                    *(unsigned*)(gY1_l + di) = *reinterpret_cast<unsigned*>(&pl);
                }
            }
        }
    __syncthreads();

    #pragma unroll
    for (int i = 0; i < 4; i++) for (int j = 0; j < 4; j++) for (int r = 0; r < 4; r++) acc[i][j][r] = 0.f;

    #pragma unroll
    for (int c = 0; c < 7; c++) {
        cpa_wait<0>();
        __syncthreads();
        if (c < 6) loadA(c+1, (c+1)&1);
        const bf16* Ah = (const bf16*)(smem + LA(c&1,0));
        const bf16* Al = (const bf16*)(smem + LA(c&1,1));
        if (c == 6) mma_k8stage<4,40,SM_STRIDE>(acc, Ah, Al, Y1h + 192*SM_STRIDE, Y1l + 192*SM_STRIDE, wm0, wn0);
        else        mma_stageG<4,2,40,SM_STRIDE>(acc, Ah, Al, Y1h + c*32*SM_STRIDE, Y1l + c*32*SM_STRIDE, wm0, wn0);
    }

    #pragma unroll
    for (int mt = 0; mt < 4; mt++)
        #pragma unroll
        for (int nt = 0; nt < 4; nt++) {
            int col = wn0 + nt*8 + tig*2;
            #pragma unroll
            for (int rh = 0; rh < 2; rh++) {
                int row = wm0 + mt*16 + g + rh*8;
                if (row < Nn) {
                    int xo = row*SM_STRIDE + col;
                    float x0 = __bfloat162float(XBh[xo])   + __bfloat162float(XBl[xo]);
                    float x1 = __bfloat162float(XBh[xo+1]) + __bfloat162float(XBl[xo+1]);
                    float v0 = 2.f*acc[mt][nt][rh*2+0] - x0;
                    float v1 = 2.f*acc[mt][nt][rh*2+1] - x1;
                    bf16 h0 = __float2bfloat16(v0), h1 = __float2bfloat16(v1);
                    bf16 l0 = __float2bfloat16(v0 - __bfloat162float(h0));
                    bf16 l1 = __float2bfloat16(v1 - __bfloat162float(h1));
                    bf162 ph; ph.x = h0; ph.y = h1;
                    bf162 pl; pl.x = l0; pl.y = l1;
                    size_t di = ((size_t)b*NP + row)*NCH + n0 + col;
                    *(unsigned*)(gY2_h + di) = *reinterpret_cast<unsigned*>(&ph);
                    *(unsigned*)(gY2_l + di) = *reinterpret_cast<unsigned*>(&pl);
                }
            }
        }
}

// ---------------- fused mix+right, 256 threads ------------------------------
// Phase 1: warp-private W pipelines (each warp owns 24 of 192 G columns).
// Phase 2: warp-private A pipeline (unchanged from R15).
#define GSTR     200
#define OFF_GH   0
#define OFF_GL   80000
#define OFF_POOL 160000
#define P1_S(hl)   (OFF_POOL + (hl)*13312)            // 64 x 104 bf16 (S, shared)
#define P1_WP      (OFF_POOL + 26624)                 // 8 warps x 2 slots x 2304
#define FUSED_SMEM (OFF_POOL + 63488)                 // 223488

__global__ __launch_bounds__(256) void k_fused(const float* __restrict__ bias,
                                               float* __restrict__ out) {
    extern __shared__ __align__(128) char smem[];
    unsigned sb = sptr(smem);
    int bi = blockIdx.x;
    int bb = bi / Nn, ii = bi % Nn;
    size_t abase = ((size_t)(bb*NP + ii))*NCH;
    int tid = threadIdx.x;
    int lane = tid & 31, warp = tid >> 5;
    int g = lane >> 2, tig = lane & 3;

    bf16* Ghp = (bf16*)(smem + OFF_GH);
    bf16* Glp = (bf16*)(smem + OFF_GL);

    // ---- phase 1: G[200x192] = S[200x96] @ W[96x192], warp-private W ----
    int wn0c = warp*24;                        // this warp's G column base
    unsigned WP = sb + P1_WP + warp*4608;      // 2 slots x 2304 B

    // warp-private W chunk load: 48 k-rows x 24 n-cols, h->slot0, l->slot1 etc.
    auto issueW = [&](int ch, int isL, int slot) {
        const bf16* src = isL ? gW_l : gW_h;
        unsigned dst = WP + slot*2304;
        #pragma unroll
        for (int i = 0; i < 5; i++) {
            int v = lane + i*32;
            if (v < 144) {
                int r = v/3, s = v%3;
                CPA(dst + r*48 + s*16, src + (size_t)(ch*48 + r)*GW + wn0c + s*8, 16);
            }
        }
        CPA_COMMIT();
    };

    const bf16* Sh = (const bf16*)(smem + P1_S(0));
    const bf16* Sl = (const bf16*)(smem + P1_S(1));

    for (int qp = 0; qp < 4; qp++) {
        int q0 = qp*64;
        __syncthreads();    // prior-qp S reads complete
        // S loads (cooperative, one commit group)
        #pragma unroll
        for (int i = 0; i < 3; i++) {
            int u = tid + i*256;
            int r = u / 12, s = u % 12;
            int q = q0 + r;
            int seg = s >> 2, cc = (s & 3)*8;
            int sz = (q < Nn) ? 16 : 0;
            int qq = (q < Nn) ? q : 0;
            size_t off = abase + (size_t)qq*32 + cc;
            const bf16 *ph, *pl;
            if (seg == 0)      { ph = gX_h  + off; pl = gX_l  + off; }
            else if (seg == 1) { ph = gY1_h + off; pl = gY1_l + off; }
            else               { ph = gY2_h + off; pl = gY2_l + off; }
            unsigned d = r*208 + s*16;
            CPA(sb + P1_S(0) + d, ph, sz);
            CPA(sb + P1_S(1) + d, pl, sz);
        }
        CPA_COMMIT();
        issueW(0, 0, 0);    // chunk0 h
        issueW(0, 1, 1);    // chunk0 l
        cpa_wait<2>();      // S arrived (W0h, W0l outstanding)
        __syncthreads();    // S visible block-wide

        float acc[4][3][4];
        #pragma unroll
        for (int i = 0; i < 4; i++) for (int j = 0; j < 3; j++) for (int r = 0; r < 4; r++) acc[i][j][r] = 0.f;

        #pragma unroll
        for (int ch = 0; ch < 2; ch++) {
            cpa_wait<0>();
            __syncwarp();
            const bf16* Wh = (const bf16*)(smem + P1_WP + warp*4608);
            const bf16* Wl = (const bf16*)(smem + P1_WP + warp*4608 + 2304);
            #pragma unroll
            for (int ks = 0; ks < 3; ks++) {
                int kb = ch*48 + ks*16;
                unsigned aH[4][4], aL[4][4];
                #pragma unroll
                for (int mt = 0; mt < 4; mt++) {
                    int r = mt*16 + (lane & 15);
                    LDA4(aH[mt], sptr(Sh + r*104 + kb + (lane >> 4)*8));
                    LDA4(aL[mt], sptr(Sl + r*104 + kb + (lane >> 4)*8));
                }
                int rr = ks*16 + (lane & 15);
                unsigned bh[3][2], bl[3][2];
                #pragma unroll
                for (int nt = 0; nt < 3; nt++) {
                    LDB2(bh[nt], sptr(Wh + rr*24 + nt*8));
                    LDB2(bl[nt], sptr(Wl + rr*24 + nt*8));
                }
                #pragma unroll
                for (int mt = 0; mt < 4; mt++)
                    #pragma unroll
                    for (int nt = 0; nt < 3; nt++) {
                        mma_bf16(acc[mt][nt], aH[mt], bh[nt]);
                        mma_bf16(acc[mt][nt], aH[mt], bl[nt]);
                        mma_bf16(acc[mt][nt], aL[mt], bh[nt]);
                    }
            }
            if (ch == 0) { issueW(1, 0, 0); issueW(1, 1, 1); }  // reuse slots (reads done)
        }

        // store this warp's G block: rows q0..q0+63, cols wn0c..wn0c+23
        #pragma unroll
        for (int mt = 0; mt < 4; mt++)
            #pragma unroll
            for (int nt = 0; nt < 3; nt++) {
                int col = wn0c + nt*8 + tig*2;
                #pragma unroll
                for (int rh = 0; rh < 2; rh++) {
                    int row = q0 + mt*16 + g + rh*8;
                    if (row < Nn) {
                        float v0 = acc[mt][nt][rh*2+0], v1 = acc[mt][nt][rh*2+1];
                        bf16 h0 = __float2bfloat16(v0), h1 = __float2bfloat16(v1);
                        bf16 l0 = __float2bfloat16(v0 - __bfloat162float(h0));
                        bf16 l1 = __float2bfloat16(v1 - __bfloat162float(h1));
                        bf162 ph; ph.x = h0; ph.y = h1;
                        bf162 pl; pl.x = l0; pl.y = l1;
                        *(bf162*)(Ghp + row*GSTR + col) = ph;
                        *(bf162*)(Glp + row*GSTR + col) = pl;
                    }
                }
            }
    }

    __syncthreads();   // G complete; no block barriers below

    // ---- phase 2: warp-private A, 3-slot ring, single-B-read ----
    unsigned PA = sb + OFF_POOL + warp*6912;   // 3 slots x 2304 B

    for (int jt = 0; jt < 2; jt++) {
        int jr = jt*128 + warp*16;
        float acc[8][4];
        #pragma unroll
        for (int j = 0; j < 8; j++) for (int r = 0; r < 4; r++) acc[j][r] = 0.f;

        auto issueLd = [&](int li) {
            int c = li >> 1, isL = li & 1;
            int phse = c >> 2, kc = c & 3;
            const bf16* src = isL ? (phse ? gR2_l : gRt_l) : (phse ? gR2_h : gRt_h);
            unsigned dst = PA + (li % 3)*2304;
            if (kc < 3) {
                int kq = kc*64;
                #pragma unroll
                for (int i = 0; i < 4; i++) {
                    int idx = lane + i*32, r = idx >> 3, s = idx & 7;
                    CPA(dst + r*144 + s*16, src + (size_t)(jr + r)*NP + kq + s*8, 16);
                }
            } else {
                if (lane < 16) CPA(dst + lane*144, src + (size_t)(jr + lane)*NP + 192, 16);
            }
            CPA_COMMIT();
        };

        issueLd(0); issueLd(1); issueLd(2);

        #pragma unroll
        for (int c = 0; c < 8; c++) {
            int phse = c >> 2, kc = c & 3;
            int coff = phse ? 128 : 64;
            const bf16* Ah = (const bf16*)(smem + OFF_POOL + warp*6912 + ((2*c) % 3)*2304);
            const bf16* Al = (const bf16*)(smem + OFF_POOL + warp*6912 + ((2*c + 1) % 3)*2304);

            if (c == 7) cpa_wait<0>(); else cpa_wait<1>();
            __syncwarp();

            if (kc < 3) {
                #pragma unroll
                for (int ks = 0; ks < 4; ks++) {
                    unsigned a4h[4], a4l[4];
                    LDA4(a4h, sptr(Ah + (lane & 15)*72 + ks*16 + (lane >> 4)*8));
                    LDA4(a4l, sptr(Al + (lane & 15)*72 + ks*16 + (lane >> 4)*8));
                    int rr = kc*64 + ks*16 + (lane & 15);
                    #pragma unroll
                    for (int nt = 0; nt < 8; nt++) {
                        unsigned bh[2], bl[2];
                        LDB2(bh, sptr(Ghp + rr*GSTR + coff + nt*8));
                        LDB2(bl, sptr(Glp + rr*GSTR + coff + nt*8));
                        mma_bf16(acc[nt], a4h, bh);
                        mma_bf16(acc[nt], a4h, bl);
                        mma_bf16(acc[nt], a4l, bh);
                    }
                }
            } else {
                unsigned a2h[2], a2l[2];
                LDA2(a2h, sptr(Ah + (lane & 15)*72));
                LDA2(a2l, sptr(Al + (lane & 15)*72));
                int rr = 192 + (lane & 7);
                #pragma unroll
                for (int nt = 0; nt < 8; nt++) {
                    unsigned bh, bl;
                    LDB1(bh, sptr(Ghp + rr*GSTR + coff + nt*8));
                    LDB1(bl, sptr(Glp + rr*GSTR + coff + nt*8));
                    mma_bf16_k8(acc[nt], a2h, bh);
                    mma_bf16_k8(acc[nt], a2h, bl);
                    mma_bf16_k8(acc[nt], a2l, bh);
                }
            }

            if (c < 7) { issueLd(2*c + 3); if (c < 6) issueLd(2*c + 4); }
        }

        #pragma unroll
        for (int nt = 0; nt < 8; nt++) {
            int o = nt*8 + tig*2;
            #pragma unroll
            for (int rh = 0; rh < 2; rh++) {
                int j = jr + g + rh*8;
                if (j < Nn) {
                    float v0 = acc[nt][rh*2+0], v1 = acc[nt][rh*2+1];
                    int gr = j*GSTR;
                    float g0a = __bfloat162float(Ghp[gr + o])       + __bfloat162float(Glp[gr + o]);
                    float g0b = __bfloat162float(Ghp[gr + o + 1])   + __bfloat162float(Glp[gr + o + 1]);
                    float g2a = __bfloat162float(Ghp[gr + 128 + o]) + __bfloat162float(Glp[gr + 128 + o]);
                    float g2b = __bfloat162float(Ghp[gr + 128 + o + 1]) + __bfloat162float(Glp[gr + 128 + o + 1]);
                    size_t oi = ((size_t)bi*Nn + j)*64 + o;
                    out[oi]     = bias[o]     + g0a - g2a + v0;
                    out[oi + 1] = bias[o + 1] + g0b - g2b + v1;
                }
            }
        }
    }
}

// ---------------------------------------------------------------------------
extern "C" void kernel_launch(void* const* d_in, const int* in_sizes, int n_in,
                              void* d_out, int out_size) {
    const float* x    = (const float*)d_in[0];
    const float* adj  = (const float*)d_in[1];
    const float* w    = (const float*)d_in[2];
    const float* bias = (const float*)d_in[3];
    float* out = (float*)d_out;

    cudaFuncSetAttribute(k_leftfused, cudaFuncAttributeMaxDynamicSharedMemorySize, LEFT_SMEM);
    cudaFuncSetAttribute(k_fused,     cudaFuncAttributeMaxDynamicSharedMemorySize, FUSED_SMEM);

    k_deg<<<Nn, 256>>>(adj);
    k_buildA<<<(NP*NP + 255)/256, 256>>>(adj);
    k_R2<<<dim3(16, 16), dim3(16, 16)>>>();
    k_prepsplit<<<768 + 12800 + 96, 256>>>(x, w);

    k_leftfused<<<dim3(100, Bx), 256, LEFT_SMEM>>>();
    k_fused<<<1600, 256, FUSED_SMEM>>>(bias, out);
}